// round 7
// baseline (speedup 1.0000x reference)
#include <cuda_runtime.h>
#include <cuda_fp16.h>
#include <stdint.h>
#include <math.h>

#define BATCH 2048
#define SEQ   80
#define EMBED 100
#define UNITS 512
#define VOCAB 10000

// ---------------- device globals (no allocation allowed) ----------------
__device__ float g_T[VOCAB * UNITS];            // emb@Wx0+b0 table (fp32, exact)
__device__ __half g_s[3][2][BATCH * UNITS];     // [layer][phase] fp16 states
__device__ __half g_W[5][UNITS * UNITS];        // transposed fp16 weights [n][k]:
                                                // 0=Wh0 1=Wx1 2=Wh1 3=Wx2 4=Wh2
__device__ int g_bar[3][16];                    // [layer][m-group] monotonic barriers

// ---------------- helpers ----------------
__device__ __forceinline__ uint32_t smem_u32(const void* p) {
    uint32_t a;
    asm("{ .reg .u64 t; cvta.to.shared.u64 t, %1; cvt.u32.u64 %0, t; }" : "=r"(a) : "l"(p));
    return a;
}

__device__ __forceinline__ uint32_t swz(uint32_t off) {
    return off ^ ((off >> 3) & 0x70);   // SW128: 8-row period, 16B granules
}

#define CP16(dst, src) \
    asm volatile("cp.async.cg.shared.global [%0], [%1], 16;" :: "r"(dst), "l"(src) : "memory")

__device__ __forceinline__ void ldsm4(uint32_t (&r)[4], uint32_t addr) {
    asm volatile("ldmatrix.sync.aligned.m8n8.x4.shared.b16 {%0,%1,%2,%3}, [%4];"
        : "=r"(r[0]), "=r"(r[1]), "=r"(r[2]), "=r"(r[3]) : "r"(addr));
}

__device__ __forceinline__ void mma16816(float (&d)[4], const uint32_t (&a)[4],
                                         const uint32_t* b) {
    asm volatile(
        "mma.sync.aligned.m16n8k16.row.col.f32.f16.f16.f32 "
        "{%0,%1,%2,%3}, {%4,%5,%6,%7}, {%8,%9}, {%0,%1,%2,%3};"
        : "+f"(d[0]), "+f"(d[1]), "+f"(d[2]), "+f"(d[3])
        : "r"(a[0]), "r"(a[1]), "r"(a[2]), "r"(a[3]), "r"(b[0]), "r"(b[1]));
}

__device__ __forceinline__ float fast_tanh(float x) {
    float e = __expf(2.0f * x);
    return 1.0f - __fdividef(2.0f, e + 1.0f);
}

// Stage = one K-64 chunk: A(128x64)=16KB @ +0, B(64x64)=8KB @ +16384
#define STAGE_SZ 24576u
#define NSTAGE   3
#define WH_OFF   (NSTAGE * STAGE_SZ)            // 73728: Wh1 (64KB), Wh2 (64KB)
#define SMEM_BYTES (WH_OFF + 2 * 65536)         // 204800 (<= 227KB dyn smem cap)

// ---------------------------------------------------------------------------
// xproj: g_T = emb @ Wx0 + b0   (fp32, M=10000 K=100 N=512)
// ---------------------------------------------------------------------------
__global__ void __launch_bounds__(256)
xproj_kernel(const float* __restrict__ emb, const float* __restrict__ Wx0,
             const float* __restrict__ b0)
{
    __shared__ float As[20][68];
    __shared__ float Bs[20][68];
    const int m0 = blockIdx.x * 64, n0 = blockIdx.y * 64;
    const int tid = threadIdx.x, tx = tid & 15, ty = tid >> 4;
    float acc[4][4] = {};
    for (int k0 = 0; k0 < EMBED; k0 += 20) {
        for (int i = tid; i < 64 * 20; i += 256) {
            int m = i / 20, k = i % 20;
            int gm = m0 + m;
            As[k][m] = (gm < VOCAB) ? emb[gm * EMBED + k0 + k] : 0.0f;
        }
        for (int i = tid; i < 20 * 64; i += 256) {
            int k = i / 64, n = i % 64;
            Bs[k][n] = Wx0[(k0 + k) * UNITS + n0 + n];
        }
        __syncthreads();
        #pragma unroll
        for (int kk = 0; kk < 20; ++kk) {
            float a[4], b[4];
            #pragma unroll
            for (int i = 0; i < 4; ++i) a[i] = As[kk][ty * 4 + i];
            #pragma unroll
            for (int j = 0; j < 4; ++j) b[j] = Bs[kk][tx * 4 + j];
            #pragma unroll
            for (int i = 0; i < 4; ++i)
                #pragma unroll
                for (int j = 0; j < 4; ++j)
                    acc[i][j] = fmaf(a[i], b[j], acc[i][j]);
        }
        __syncthreads();
    }
    #pragma unroll
    for (int i = 0; i < 4; ++i) {
        int row = m0 + ty * 4 + i;
        if (row >= VOCAB) continue;
        #pragma unroll
        for (int j = 0; j < 4; ++j) {
            int col = n0 + tx * 4 + j;
            g_T[row * UNITS + col] = acc[i][j] + b0[col];
        }
    }
}

// ---------------------------------------------------------------------------
// transpose + convert weights: g_W[m][n*512+k] = fp16(W[k*512+n])
// ---------------------------------------------------------------------------
__global__ void __launch_bounds__(256)
conv_weights(const float* __restrict__ a0, const float* __restrict__ a1,
             const float* __restrict__ a2, const float* __restrict__ a3,
             const float* __restrict__ a4)
{
    int i = blockIdx.x * 256 + threadIdx.x;   // i = k*512+n
    int k = i >> 9, n = i & 511;
    const float* src[5] = {a0, a1, a2, a3, a4};
    #pragma unroll
    for (int m = 0; m < 5; ++m)
        g_W[m][n * UNITS + k] = __float2half_rn(src[m][i]);
}

__global__ void init_states()
{
    int i = blockIdx.x * blockDim.x + threadIdx.x;
    const __half z = __float2half(0.0f);
    #pragma unroll
    for (int l = 0; l < 3; ++l)
        g_s[l][0][i] = z;
    if (i < 48) (&g_bar[0][0])[i] = 0;   // reset barriers every launch/replay
}

// ---------------------------------------------------------------------------
// m-group barrier: poll until g_bar[l][grp] >= target (monotonic counter)
// ---------------------------------------------------------------------------
__device__ __forceinline__ void bar_wait(int l, int grp, int target, int tid)
{
    if (tid == 0) {
        unsigned ns = 4;
        for (;;) {
            int v;
            asm volatile("ld.acquire.gpu.s32 %0, [%1];"
                         : "=r"(v) : "l"(&g_bar[l][grp]));
            if (v >= target) break;
            __nanosleep(ns);
            if (ns < 64) ns <<= 1;
        }
    }
    __syncthreads();
}

// ---------------------------------------------------------------------------
// chunk loader (K=64): A always staged; B staged only for X-part / layer 0
// ---------------------------------------------------------------------------
__device__ __forceinline__ void load_chunk(uint32_t sb, int layer, int c,
    const __half* __restrict__ Aw, const __half* __restrict__ Ax,
    const __half* __restrict__ Bx, int m0, int n0, int tid)
{
    const uint32_t stg = sb + (uint32_t)(c % NSTAGE) * STAGE_SZ;
    const bool xpart = (layer == 0) || (c >= 8);
    const __half* A = (layer > 0 && c >= 8) ? Ax : Aw;
    const int k0 = (c & 7) * 64;
    #pragma unroll
    for (int i = 0; i < 4; ++i) {                 // A: 128 rows x 64 k
        int idx = tid + i * 256;
        int row = idx >> 3, g = idx & 7;
        uint32_t d = swz((uint32_t)(row * 128 + g * 16));
        CP16(stg + d, A + (size_t)(m0 + row) * UNITS + k0 + g * 8);
    }
    if (xpart) {
        #pragma unroll
        for (int i = 0; i < 2; ++i) {             // B: 64 rows x 64 k
            int idx = tid + i * 256;
            int row = idx >> 3, g = idx & 7;
            uint32_t d = swz((uint32_t)(row * 128 + g * 16));
            CP16(stg + 16384u + d, Bx + (size_t)(n0 + row) * UNITS + k0 + g * 8);
        }
    }
    asm volatile("cp.async.commit_group;" ::: "memory");
}

// ---------------------------------------------------------------------------
// persistent RNN: grid (8 n, 16 m) = 128 co-resident CTAs (1/SM, wave-1).
// Layer l>=1 computes the Wh-part first (barrier-free, B resident in smem),
// waits for o_{l-1}(t) mid-loop (buried under Wh compute), then the Wx-part.
// ---------------------------------------------------------------------------
__global__ void __launch_bounds__(256)
rnn_persistent(const int* __restrict__ tokens,
               const float* __restrict__ b1, const float* __restrict__ b2)
{
    extern __shared__ __align__(1024) char smem[];
    const uint32_t sb = smem_u32(smem);
    const int tid = threadIdx.x, wid = tid >> 5, lane = tid & 31;
    const int n0 = blockIdx.x * 64, m0 = blockIdx.y * 128;
    const int grp = blockIdx.y;

    // warp layout: 4 m-warps x 2 n-warps; warp tile 32x32
    const int wm = (wid & 3) * 32;
    const int wn = (wid >> 2) * 32;
    const int sel = lane >> 3, rowin = lane & 7;
    const int a_row  = wm + (sel & 1) * 8 + rowin;
    const int a_colb = (sel >> 1) * 16;
    const int b_row  = wn + (sel >> 1) * 8 + rowin;
    const int b_colb = (sel & 1) * 16;
    const int grpq = lane >> 2, qd = (lane & 3) * 2;

    // ---- one-time: load resident Wh1, Wh2 n-slices (same layout as staged B) ----
    #pragma unroll
    for (int m = 0; m < 2; ++m) {
        const __half* src = g_W[m ? 4 : 2];                 // Wh1, Wh2
        const uint32_t base = sb + WH_OFF + (uint32_t)m * 65536u;
        #pragma unroll
        for (int hh = 0; hh < 8; ++hh)
            #pragma unroll
            for (int i = 0; i < 2; ++i) {
                int idx = tid + i * 256;
                int row = idx >> 3, g = idx & 7;
                uint32_t d = swz((uint32_t)(row * 128 + g * 16));
                CP16(base + hh * 8192u + d,
                     src + (size_t)(n0 + row) * UNITS + hh * 64 + g * 8);
            }
    }
    asm volatile("cp.async.commit_group;" ::: "memory");
    asm volatile("cp.async.wait_group 0;" ::: "memory");
    __syncthreads();

    for (int t = 0; t < SEQ; ++t) {
        const int p = t & 1;
        #pragma unroll 1
        for (int layer = 0; layer < 3; ++layer) {
            const __half *Aw, *Ax = nullptr, *Bx;
            uint32_t whb = 0;
            const float* bias = nullptr;
            int NC;
            if (layer == 0) {
                NC = 8;
                Aw = g_s[0][p];                  // s0(t-1)
                Bx = g_W[0];                     // Wh0 (staged)
            } else {
                NC = 16;
                Aw = g_s[layer][p];              // s_l(t-1): Wh part (chunks 0-7)
                Ax = g_s[layer - 1][p ^ 1];      // o_{l-1}(t): Wx part (chunks 8-15)
                Bx = g_W[layer == 1 ? 1 : 3];    // Wx_l (staged)
                whb = sb + WH_OFF + (uint32_t)(layer - 1) * 65536u;
                bias = (layer == 1) ? b1 : b2;
            }
            __half* outp = g_s[layer][p ^ 1];

            // pre-satisfied in steady state: own previous step complete
            bar_wait(layer, grp, 8 * t, tid);

            load_chunk(sb, layer, 0, Aw, Ax, Bx, m0, n0, tid);
            load_chunk(sb, layer, 1, Aw, Ax, Bx, m0, n0, tid);

            float acc[2][4][4] = {};

            for (int c = 0; c < NC; ++c) {
                asm volatile("cp.async.wait_group 1;" ::: "memory");
                __syncthreads();

                const int nc = c + 2;
                if (nc < NC) {
                    if (layer > 0 && nc == 8)    // hot wait, buried under Wh compute
                        bar_wait(layer - 1, grp, 8 * (t + 1), tid);
                    load_chunk(sb, layer, nc, Aw, Ax, Bx, m0, n0, tid);
                } else {
                    asm volatile("cp.async.commit_group;" ::: "memory");
                }

                const uint32_t stg = sb + (uint32_t)(c % NSTAGE) * STAGE_SZ;
                const uint32_t Ab = stg;
                const uint32_t Bb = (layer > 0 && c < 8)
                                        ? (whb + (uint32_t)c * 8192u)
                                        : (stg + 16384u);
                #pragma unroll
                for (int ks = 0; ks < 4; ++ks) {
                    uint32_t a[2][4], b[2][4];
                    #pragma unroll
                    for (int mt = 0; mt < 2; ++mt) {
                        uint32_t off = swz((uint32_t)((a_row + mt * 16) * 128 + a_colb + ks * 32));
                        ldsm4(a[mt], Ab + off);
                    }
                    #pragma unroll
                    for (int bt = 0; bt < 2; ++bt) {
                        uint32_t off = swz((uint32_t)((b_row + bt * 16) * 128 + b_colb + ks * 32));
                        ldsm4(b[bt], Bb + off);
                    }
                    #pragma unroll
                    for (int mt = 0; mt < 2; ++mt)
                        #pragma unroll
                        for (int j = 0; j < 4; ++j)
                            mma16816(acc[mt][j], a[mt], &b[j >> 1][(j & 1) * 2]);
                }
            }

            // ---- epilogue: add T/bias, tanh, fp16 store ----
            #pragma unroll
            for (int mt = 0; mt < 2; ++mt) {
                const int r0 = m0 + wm + mt * 16 + grpq;
                const int r1 = r0 + 8;
                const float *t0, *t1;
                if (layer == 0) {
                    t0 = g_T + (size_t)tokens[(size_t)r0 * SEQ + t] * UNITS;
                    t1 = g_T + (size_t)tokens[(size_t)r1 * SEQ + t] * UNITS;
                } else {
                    t0 = bias; t1 = bias;
                }
                #pragma unroll
                for (int j = 0; j < 4; ++j) {
                    const int c = n0 + wn + j * 8 + qd;
                    float2 ad0 = *(const float2*)(t0 + c);
                    float2 ad1 = *(const float2*)(t1 + c);
                    __half2 p0 = __floats2half2_rn(fast_tanh(acc[mt][j][0] + ad0.x),
                                                   fast_tanh(acc[mt][j][1] + ad0.y));
                    __half2 p1 = __floats2half2_rn(fast_tanh(acc[mt][j][2] + ad1.x),
                                                   fast_tanh(acc[mt][j][3] + ad1.y));
                    *reinterpret_cast<__half2*>(outp + (size_t)r0 * UNITS + c) = p0;
                    *reinterpret_cast<__half2*>(outp + (size_t)r1 * UNITS + c) = p1;
                }
            }

            __syncthreads();                 // all stores done before signal
            if (tid == 0) {
                __threadfence();
                atomicAdd(&g_bar[layer][grp], 1);
            }
        }
    }
}

// ---------------------------------------------------------------------------
// head: out[b] = sigmoid( s2[b,:] . Wout + bout )
// ---------------------------------------------------------------------------
__global__ void __launch_bounds__(256)
head_kernel(const float* __restrict__ Wout, const float* __restrict__ bout,
            float* __restrict__ out)
{
    const __half* s2 = g_s[2][0];   // SEQ even -> final state in phase 0
    int row  = blockIdx.x * 8 + (threadIdx.x >> 5);
    int lane = threadIdx.x & 31;
    float sum = 0.0f;
    #pragma unroll 4
    for (int k = lane; k < UNITS; k += 32)
        sum += __half2float(s2[(size_t)row * UNITS + k]) * Wout[k];
    #pragma unroll
    for (int o = 16; o; o >>= 1)
        sum += __shfl_xor_sync(0xFFFFFFFFu, sum, o);
    if (lane == 0) {
        float logit = sum + bout[0];
        out[row] = __fdividef(1.0f, 1.0f + __expf(-logit));
    }
}

// ---------------------------------------------------------------------------
extern "C" void kernel_launch(void* const* d_in, const int* in_sizes, int n_in,
                              void* d_out, int out_size)
{
    const int*   tokens = (const int*)  d_in[0];
    const float* emb    = (const float*)d_in[1];
    const float* Wx0    = (const float*)d_in[2];
    const float* Wh0    = (const float*)d_in[3];
    const float* b0     = (const float*)d_in[4];
    const float* Wx1    = (const float*)d_in[5];
    const float* Wh1    = (const float*)d_in[6];
    const float* b1     = (const float*)d_in[7];
    const float* Wx2    = (const float*)d_in[8];
    const float* Wh2    = (const float*)d_in[9];
    const float* b2     = (const float*)d_in[10];
    const float* Wout   = (const float*)d_in[11];
    const float* bout   = (const float*)d_in[12];
    float* out = (float*)d_out;

    cudaFuncSetAttribute(rnn_persistent, cudaFuncAttributeMaxDynamicSharedMemorySize,
                         SMEM_BYTES);

    // prologue
    xproj_kernel<<<dim3((VOCAB + 63) / 64, UNITS / 64), 256>>>(emb, Wx0, b0);
    conv_weights<<<(UNITS * UNITS) / 256, 256>>>(Wh0, Wx1, Wh1, Wx2, Wh2);
    init_states<<<(BATCH * UNITS) / 256, 256>>>();

    // the whole 80x3 recurrence in one persistent launch
    dim3 grid(UNITS / 64, BATCH / 128);   // (8 n, 16 m) = 128 CTAs, 1/SM
    rnn_persistent<<<grid, 256, SMEM_BYTES>>>(tokens, b1, b2);

    head_kernel<<<BATCH / 8, 256>>>(Wout, bout, out);
}

// round 8
// speedup vs baseline: 1.0725x; 1.0725x over previous
#include <cuda_runtime.h>
#include <cuda_fp16.h>
#include <stdint.h>
#include <math.h>

#define BATCH 2048
#define SEQ   80
#define EMBED 100
#define UNITS 512
#define VOCAB 10000

// ---------------- device globals (no allocation allowed) ----------------
__device__ float g_T[VOCAB * UNITS];            // emb@Wx0+b0 table (fp32, exact)
__device__ __half g_s[3][2][BATCH * UNITS];     // [layer][phase] fp16 states
__device__ __half g_W[5][UNITS * UNITS];        // transposed fp16 weights [n][k]:
                                                // 0=Wh0 1=Wx1 2=Wh1 3=Wx2 4=Wh2
__device__ int g_bar[32];                       // per-m-group monotonic barriers

// ---------------- helpers ----------------
__device__ __forceinline__ uint32_t smem_u32(const void* p) {
    uint32_t a;
    asm("{ .reg .u64 t; cvta.to.shared.u64 t, %1; cvt.u32.u64 %0, t; }" : "=r"(a) : "l"(p));
    return a;
}

__device__ __forceinline__ uint32_t swz(uint32_t off) {
    return off ^ ((off >> 3) & 0x70);   // SW128: 8-row period, 16B granules
}

#define CP16(dst, src) \
    asm volatile("cp.async.cg.shared.global [%0], [%1], 16;" :: "r"(dst), "l"(src) : "memory")

__device__ __forceinline__ void ldsm4(uint32_t (&r)[4], uint32_t addr) {
    asm volatile("ldmatrix.sync.aligned.m8n8.x4.shared.b16 {%0,%1,%2,%3}, [%4];"
        : "=r"(r[0]), "=r"(r[1]), "=r"(r[2]), "=r"(r[3]) : "r"(addr));
}

__device__ __forceinline__ void mma16816(float (&d)[4], const uint32_t (&a)[4],
                                         const uint32_t* b) {
    asm volatile(
        "mma.sync.aligned.m16n8k16.row.col.f32.f16.f16.f32 "
        "{%0,%1,%2,%3}, {%4,%5,%6,%7}, {%8,%9}, {%0,%1,%2,%3};"
        : "+f"(d[0]), "+f"(d[1]), "+f"(d[2]), "+f"(d[3])
        : "r"(a[0]), "r"(a[1]), "r"(a[2]), "r"(a[3]), "r"(b[0]), "r"(b[1]));
}

__device__ __forceinline__ float fast_tanh(float x) {
    float e = __expf(2.0f * x);
    return 1.0f - __fdividef(2.0f, e + 1.0f);
}

// Stage = one K-128 chunk for M-tile 64:
//   A (64x128) as two 8K halves @ +0,+8192 ; B (64x128) as two 8K halves @ +16384,+24576
#define STAGE 32768u
#define NSTAGE 3
#define SMEM_BYTES (NSTAGE * STAGE)   // 96 KB -> 2 CTAs/SM

// ---------------------------------------------------------------------------
// xproj: g_T = emb @ Wx0 + b0   (fp32, M=10000 K=100 N=512)
// ---------------------------------------------------------------------------
__global__ void __launch_bounds__(256)
xproj_kernel(const float* __restrict__ emb, const float* __restrict__ Wx0,
             const float* __restrict__ b0)
{
    __shared__ float As[20][68];
    __shared__ float Bs[20][68];
    const int m0 = blockIdx.x * 64, n0 = blockIdx.y * 64;
    const int tid = threadIdx.x, tx = tid & 15, ty = tid >> 4;
    float acc[4][4] = {};
    for (int k0 = 0; k0 < EMBED; k0 += 20) {
        for (int i = tid; i < 64 * 20; i += 256) {
            int m = i / 20, k = i % 20;
            int gm = m0 + m;
            As[k][m] = (gm < VOCAB) ? emb[gm * EMBED + k0 + k] : 0.0f;
        }
        for (int i = tid; i < 20 * 64; i += 256) {
            int k = i / 64, n = i % 64;
            Bs[k][n] = Wx0[(k0 + k) * UNITS + n0 + n];
        }
        __syncthreads();
        #pragma unroll
        for (int kk = 0; kk < 20; ++kk) {
            float a[4], b[4];
            #pragma unroll
            for (int i = 0; i < 4; ++i) a[i] = As[kk][ty * 4 + i];
            #pragma unroll
            for (int j = 0; j < 4; ++j) b[j] = Bs[kk][tx * 4 + j];
            #pragma unroll
            for (int i = 0; i < 4; ++i)
                #pragma unroll
                for (int j = 0; j < 4; ++j)
                    acc[i][j] = fmaf(a[i], b[j], acc[i][j]);
        }
        __syncthreads();
    }
    #pragma unroll
    for (int i = 0; i < 4; ++i) {
        int row = m0 + ty * 4 + i;
        if (row >= VOCAB) continue;
        #pragma unroll
        for (int j = 0; j < 4; ++j) {
            int col = n0 + tx * 4 + j;
            g_T[row * UNITS + col] = acc[i][j] + b0[col];
        }
    }
}

// ---------------------------------------------------------------------------
// transpose + convert weights: g_W[m][n*512+k] = fp16(W[k*512+n])
// ---------------------------------------------------------------------------
__global__ void __launch_bounds__(256)
conv_weights(const float* __restrict__ a0, const float* __restrict__ a1,
             const float* __restrict__ a2, const float* __restrict__ a3,
             const float* __restrict__ a4)
{
    int i = blockIdx.x * 256 + threadIdx.x;   // i = k*512+n
    int k = i >> 9, n = i & 511;
    const float* src[5] = {a0, a1, a2, a3, a4};
    #pragma unroll
    for (int m = 0; m < 5; ++m)
        g_W[m][n * UNITS + k] = __float2half_rn(src[m][i]);
}

__global__ void init_states()
{
    int i = blockIdx.x * blockDim.x + threadIdx.x;
    const __half z = __float2half(0.0f);
    #pragma unroll
    for (int l = 0; l < 3; ++l)
        g_s[l][0][i] = z;
    if (i < 32) g_bar[i] = 0;   // reset barriers on every launch/replay
}

// ---------------------------------------------------------------------------
// stage loader: A (64 x 128) + B (64 x 128) fp16, two 64-col halves each,
// SW128 swizzled 128B rows. One commit_group per stage.
// ---------------------------------------------------------------------------
__device__ __forceinline__ void load_stage(uint32_t base,
    const __half* __restrict__ A, const __half* __restrict__ B,
    int m0, int n0, int k0, int tid)
{
    #pragma unroll
    for (int h = 0; h < 2; ++h) {
        const int kh = k0 + h * 64;
        const uint32_t ab = base + h * 8192u;
        const uint32_t bb = base + 16384u + h * 8192u;
        #pragma unroll
        for (int i = 0; i < 2; ++i) {           // A half: 512 x 16B
            int idx = tid + i * 256;
            int row = idx >> 3, g = idx & 7;
            uint32_t d = swz((uint32_t)(row * 128 + g * 16));
            CP16(ab + d, A + (size_t)(m0 + row) * UNITS + kh + g * 8);
        }
        #pragma unroll
        for (int i = 0; i < 2; ++i) {           // B half: 512 x 16B
            int idx = tid + i * 256;
            int row = idx >> 3, g = idx & 7;
            uint32_t d = swz((uint32_t)(row * 128 + g * 16));
            CP16(bb + d, B + (size_t)(n0 + row) * UNITS + kh + g * 8);
        }
    }
    asm volatile("cp.async.commit_group;" ::: "memory");
}

// ---------------------------------------------------------------------------
// persistent RNN: grid (8 n, 32 m) = 256 CTAs, 2/SM (16 warps/SM).
// Each CTA owns C tile [m0:m0+64) x [n0:n0+64) for the whole sequence.
// The 8 CTAs sharing an m-group sync via a monotonic atomic barrier.
// ---------------------------------------------------------------------------
__global__ void __launch_bounds__(256, 2)
rnn_persistent(const int* __restrict__ tokens,
               const float* __restrict__ b1, const float* __restrict__ b2)
{
    extern __shared__ __align__(1024) char smem[];
    const uint32_t sb = smem_u32(smem);
    const int tid = threadIdx.x, wid = tid >> 5, lane = tid & 31;
    const int n0 = blockIdx.x * 64, m0 = blockIdx.y * 64;
    const int grp = blockIdx.y;

    // warp layout: 2 m-warps x 4 n-warps; warp tile 32x16
    const int wm = (wid & 1) * 32;
    const int wn = (wid >> 1) * 16;
    const int sel = lane >> 3, rowin = lane & 7;
    const int a_row  = wm + (sel & 1) * 8 + rowin;   // + mt*16
    const int a_colb = (sel >> 1) * 16;              // + ks*32
    const int b_row  = wn + (sel >> 1) * 8 + rowin;  // 16 n-rows
    const int b_colb = (sel & 1) * 16;               // + ks*32
    const int grpq = lane >> 2, qd = (lane & 3) * 2;

    int bidx = 0;   // barrier instance counter (uniform across threads)

    for (int t = 0; t < SEQ; ++t) {
        const int p = t & 1;
        #pragma unroll 1
        for (int layer = 0; layer < 3; ++layer) {
            const __half *A0, *B0, *A1, *B1;
            int nmat;
            const float* bias;
            if (layer == 0) {
                nmat = 1; bias = nullptr;
                A0 = g_s[0][p];  B0 = g_W[0];  A1 = A0;  B1 = B0;
            } else {
                nmat = 2;
                int wx = (layer == 1) ? 1 : 3;
                bias = (layer == 1) ? b1 : b2;
                A0 = g_s[layer - 1][p ^ 1];  B0 = g_W[wx];
                A1 = g_s[layer][p];          B1 = g_W[wx + 1];
            }
            __half* outp = g_s[layer][p ^ 1];
            const __half* Asrc[2] = {A0, A1};
            const __half* Bsrc[2] = {B0, B1};
            const int NC = nmat * 4;   // K-128 stages

            float acc[2][2][4] = {};

            // prime stages 0,1 (both in mat 0: k=0,128)
            load_stage(sb + 0 * STAGE, A0, B0, m0, n0, 0, tid);
            load_stage(sb + 1 * STAGE, A0, B0, m0, n0, 128, tid);

            for (int c = 0; c < NC; ++c) {
                asm volatile("cp.async.wait_group 1;" ::: "memory");
                __syncthreads();

                const int nc = c + 2;
                if (nc < NC) {
                    load_stage(sb + (nc % NSTAGE) * STAGE,
                               Asrc[nc >> 2], Bsrc[nc >> 2],
                               m0, n0, (nc & 3) * 128, tid);
                } else {
                    asm volatile("cp.async.commit_group;" ::: "memory");
                }

                const uint32_t stb = sb + (uint32_t)(c % NSTAGE) * STAGE;
                #pragma unroll
                for (int h = 0; h < 2; ++h) {
                    const uint32_t Ab = stb + h * 8192u;
                    const uint32_t Bb = stb + 16384u + h * 8192u;
                    #pragma unroll
                    for (int ks = 0; ks < 4; ++ks) {
                        uint32_t a[2][4], b[4];
                        #pragma unroll
                        for (int mt = 0; mt < 2; ++mt) {
                            uint32_t off = swz((uint32_t)((a_row + mt * 16) * 128 + a_colb + ks * 32));
                            ldsm4(a[mt], Ab + off);
                        }
                        {
                            uint32_t off = swz((uint32_t)(b_row * 128 + b_colb + ks * 32));
                            ldsm4(b, Bb + off);
                        }
                        #pragma unroll
                        for (int mt = 0; mt < 2; ++mt)
                            #pragma unroll
                            for (int j = 0; j < 2; ++j)
                                mma16816(acc[mt][j], a[mt], &b[j * 2]);
                    }
                }
            }

            // ---- epilogue: add T/bias, tanh, fp16 store ----
            #pragma unroll
            for (int mt = 0; mt < 2; ++mt) {
                const int r0 = m0 + wm + mt * 16 + grpq;
                const int r1 = r0 + 8;
                const float *t0, *t1;
                if (layer == 0) {
                    t0 = g_T + (size_t)tokens[(size_t)r0 * SEQ + t] * UNITS;
                    t1 = g_T + (size_t)tokens[(size_t)r1 * SEQ + t] * UNITS;
                } else {
                    t0 = bias; t1 = bias;
                }
                #pragma unroll
                for (int j = 0; j < 2; ++j) {
                    const int c = n0 + wn + j * 8 + qd;
                    float2 ad0 = *(const float2*)(t0 + c);
                    float2 ad1 = *(const float2*)(t1 + c);
                    __half2 p0 = __floats2half2_rn(fast_tanh(acc[mt][j][0] + ad0.x),
                                                   fast_tanh(acc[mt][j][1] + ad0.y));
                    __half2 p1 = __floats2half2_rn(fast_tanh(acc[mt][j][2] + ad1.x),
                                                   fast_tanh(acc[mt][j][3] + ad1.y));
                    *reinterpret_cast<__half2*>(outp + (size_t)r0 * UNITS + c) = p0;
                    *reinterpret_cast<__half2*>(outp + (size_t)r1 * UNITS + c) = p1;
                }
            }

            // ---- m-group barrier (8 CTAs), monotonic counter ----
            ++bidx;
            __syncthreads();
            if (tid == 0) {
                __threadfence();
                atomicAdd(&g_bar[grp], 1);
                const int target = 8 * bidx;
                unsigned ns = 8;
                for (;;) {
                    int v;
                    asm volatile("ld.acquire.gpu.s32 %0, [%1];"
                                 : "=r"(v) : "l"(&g_bar[grp]));
                    if (v >= target) break;
                    __nanosleep(ns);
                    if (ns < 128) ns <<= 1;
                }
            }
            __syncthreads();
        }
    }
}

// ---------------------------------------------------------------------------
// head: out[b] = sigmoid( s2[b,:] . Wout + bout )
// ---------------------------------------------------------------------------
__global__ void __launch_bounds__(256)
head_kernel(const float* __restrict__ Wout, const float* __restrict__ bout,
            float* __restrict__ out)
{
    const __half* s2 = g_s[2][0];   // SEQ even -> final state in phase 0
    int row  = blockIdx.x * 8 + (threadIdx.x >> 5);
    int lane = threadIdx.x & 31;
    float sum = 0.0f;
    #pragma unroll 4
    for (int k = lane; k < UNITS; k += 32)
        sum += __half2float(s2[(size_t)row * UNITS + k]) * Wout[k];
    #pragma unroll
    for (int o = 16; o; o >>= 1)
        sum += __shfl_xor_sync(0xFFFFFFFFu, sum, o);
    if (lane == 0) {
        float logit = sum + bout[0];
        out[row] = __fdividef(1.0f, 1.0f + __expf(-logit));
    }
}

// ---------------------------------------------------------------------------
extern "C" void kernel_launch(void* const* d_in, const int* in_sizes, int n_in,
                              void* d_out, int out_size)
{
    const int*   tokens = (const int*)  d_in[0];
    const float* emb    = (const float*)d_in[1];
    const float* Wx0    = (const float*)d_in[2];
    const float* Wh0    = (const float*)d_in[3];
    const float* b0     = (const float*)d_in[4];
    const float* Wx1    = (const float*)d_in[5];
    const float* Wh1    = (const float*)d_in[6];
    const float* b1     = (const float*)d_in[7];
    const float* Wx2    = (const float*)d_in[8];
    const float* Wh2    = (const float*)d_in[9];
    const float* b2     = (const float*)d_in[10];
    const float* Wout   = (const float*)d_in[11];
    const float* bout   = (const float*)d_in[12];
    float* out = (float*)d_out;

    cudaFuncSetAttribute(rnn_persistent, cudaFuncAttributeMaxDynamicSharedMemorySize,
                         SMEM_BYTES);

    // prologue
    xproj_kernel<<<dim3((VOCAB + 63) / 64, UNITS / 64), 256>>>(emb, Wx0, b0);
    conv_weights<<<(UNITS * UNITS) / 256, 256>>>(Wh0, Wx1, Wh1, Wx2, Wh2);
    init_states<<<(BATCH * UNITS) / 256, 256>>>();

    // the whole 80x3 recurrence in one persistent launch
    dim3 grid(UNITS / 64, BATCH / 64);   // (8 n, 32 m) = 256 CTAs, 2/SM
    rnn_persistent<<<grid, 256, SMEM_BYTES>>>(tokens, b1, b2);

    head_kernel<<<BATCH / 8, 256>>>(Wout, bout, out);
}

// round 9
// speedup vs baseline: 1.1157x; 1.0403x over previous
#include <cuda_runtime.h>
#include <cuda_fp16.h>
#include <stdint.h>
#include <math.h>

#define BATCH 2048
#define SEQ   80
#define EMBED 100
#define UNITS 512
#define VOCAB 10000

// ---------------- device globals (no allocation allowed) ----------------
__device__ float g_T[VOCAB * UNITS];            // emb@Wx0+b0 table (fp32, exact)
__device__ __half g_s[3][2][BATCH * UNITS];     // [layer][phase] fp16 states
__device__ __half g_W[5][UNITS * UNITS];        // transposed fp16 weights [n][k]:
                                                // 0=Wh0 1=Wx1 2=Wh1 3=Wx2 4=Wh2
__device__ int g_bar[16];                       // per-m-group monotonic barriers

// ---------------- helpers ----------------
__device__ __forceinline__ uint32_t smem_u32(const void* p) {
    uint32_t a;
    asm("{ .reg .u64 t; cvta.to.shared.u64 t, %1; cvt.u32.u64 %0, t; }" : "=r"(a) : "l"(p));
    return a;
}

__device__ __forceinline__ uint32_t swz(uint32_t off) {
    return off ^ ((off >> 3) & 0x70);   // SW128: 8-row period, 16B granules
}

#define CP16(dst, src) \
    asm volatile("cp.async.cg.shared.global [%0], [%1], 16;" :: "r"(dst), "l"(src) : "memory")

__device__ __forceinline__ void ldsm4(uint32_t (&r)[4], uint32_t addr) {
    asm volatile("ldmatrix.sync.aligned.m8n8.x4.shared.b16 {%0,%1,%2,%3}, [%4];"
        : "=r"(r[0]), "=r"(r[1]), "=r"(r[2]), "=r"(r[3]) : "r"(addr));
}

__device__ __forceinline__ void mma16816(float (&d)[4], const uint32_t (&a)[4],
                                         const uint32_t* b) {
    asm volatile(
        "mma.sync.aligned.m16n8k16.row.col.f32.f16.f16.f32 "
        "{%0,%1,%2,%3}, {%4,%5,%6,%7}, {%8,%9}, {%0,%1,%2,%3};"
        : "+f"(d[0]), "+f"(d[1]), "+f"(d[2]), "+f"(d[3])
        : "r"(a[0]), "r"(a[1]), "r"(a[2]), "r"(a[3]), "r"(b[0]), "r"(b[1]));
}

__device__ __forceinline__ float fast_tanh(float x) {
    float e = __expf(2.0f * x);
    return 1.0f - __fdividef(2.0f, e + 1.0f);
}

// Stage = one K-128 chunk: A(128x128) two 16K halves @ +0,+16384;
//                          B(64x128) two 8K halves @ +32768,+40960 (when staged)
#define STAGE 49152u
#define NSTAGE 2
#define WH_OFF (NSTAGE * STAGE)                 // 98304: resident Wh1(64K), Wh2(64K)
#define SMEM_BYTES (WH_OFF + 2 * 65536)         // 229376 (<= 232448 cap)

// ---------------------------------------------------------------------------
// xproj: g_T = emb @ Wx0 + b0   (fp32, M=10000 K=100 N=512)
// ---------------------------------------------------------------------------
__global__ void __launch_bounds__(256)
xproj_kernel(const float* __restrict__ emb, const float* __restrict__ Wx0,
             const float* __restrict__ b0)
{
    __shared__ float As[20][68];
    __shared__ float Bs[20][68];
    const int m0 = blockIdx.x * 64, n0 = blockIdx.y * 64;
    const int tid = threadIdx.x, tx = tid & 15, ty = tid >> 4;
    float acc[4][4] = {};
    for (int k0 = 0; k0 < EMBED; k0 += 20) {
        for (int i = tid; i < 64 * 20; i += 256) {
            int m = i / 20, k = i % 20;
            int gm = m0 + m;
            As[k][m] = (gm < VOCAB) ? emb[gm * EMBED + k0 + k] : 0.0f;
        }
        for (int i = tid; i < 20 * 64; i += 256) {
            int k = i / 64, n = i % 64;
            Bs[k][n] = Wx0[(k0 + k) * UNITS + n0 + n];
        }
        __syncthreads();
        #pragma unroll
        for (int kk = 0; kk < 20; ++kk) {
            float a[4], b[4];
            #pragma unroll
            for (int i = 0; i < 4; ++i) a[i] = As[kk][ty * 4 + i];
            #pragma unroll
            for (int j = 0; j < 4; ++j) b[j] = Bs[kk][tx * 4 + j];
            #pragma unroll
            for (int i = 0; i < 4; ++i)
                #pragma unroll
                for (int j = 0; j < 4; ++j)
                    acc[i][j] = fmaf(a[i], b[j], acc[i][j]);
        }
        __syncthreads();
    }
    #pragma unroll
    for (int i = 0; i < 4; ++i) {
        int row = m0 + ty * 4 + i;
        if (row >= VOCAB) continue;
        #pragma unroll
        for (int j = 0; j < 4; ++j) {
            int col = n0 + tx * 4 + j;
            g_T[row * UNITS + col] = acc[i][j] + b0[col];
        }
    }
}

// ---------------------------------------------------------------------------
// transpose + convert weights: g_W[m][n*512+k] = fp16(W[k*512+n])
// ---------------------------------------------------------------------------
__global__ void __launch_bounds__(256)
conv_weights(const float* __restrict__ a0, const float* __restrict__ a1,
             const float* __restrict__ a2, const float* __restrict__ a3,
             const float* __restrict__ a4)
{
    int i = blockIdx.x * 256 + threadIdx.x;   // i = k*512+n
    int k = i >> 9, n = i & 511;
    const float* src[5] = {a0, a1, a2, a3, a4};
    #pragma unroll
    for (int m = 0; m < 5; ++m)
        g_W[m][n * UNITS + k] = __float2half_rn(src[m][i]);
}

__global__ void init_states()
{
    int i = blockIdx.x * blockDim.x + threadIdx.x;
    const __half z = __float2half(0.0f);
    #pragma unroll
    for (int l = 0; l < 3; ++l)
        g_s[l][0][i] = z;
    if (i < 16) g_bar[i] = 0;   // reset barriers on every launch/replay
}

// ---------------------------------------------------------------------------
// chunk loader (K=128): A (128x128) always staged; B (64x128) staged only
// when Bst != nullptr (layer-0 Wh0 / Wx chunks of layers 1-2).
// ---------------------------------------------------------------------------
__device__ __forceinline__ void load_chunk(uint32_t stg,
    const __half* __restrict__ A, const __half* __restrict__ Bst,
    int k0, int m0, int n0, int tid)
{
    #pragma unroll
    for (int h = 0; h < 2; ++h) {
        const int kh = k0 + h * 64;
        const uint32_t ab = stg + h * 16384u;
        #pragma unroll
        for (int i = 0; i < 4; ++i) {           // A half: 1024 x 16B
            int idx = tid + i * 256;
            int row = idx >> 3, g = idx & 7;
            uint32_t d = swz((uint32_t)(row * 128 + g * 16));
            CP16(ab + d, A + (size_t)(m0 + row) * UNITS + kh + g * 8);
        }
        if (Bst) {
            const uint32_t bb = stg + 32768u + h * 8192u;
            #pragma unroll
            for (int i = 0; i < 2; ++i) {       // B half: 512 x 16B
                int idx = tid + i * 256;
                int row = idx >> 3, g = idx & 7;
                uint32_t d = swz((uint32_t)(row * 128 + g * 16));
                CP16(bb + d, Bst + (size_t)(n0 + row) * UNITS + kh + g * 8);
            }
        }
    }
    asm volatile("cp.async.commit_group;" ::: "memory");
}

// ---------------------------------------------------------------------------
// persistent RNN: grid (8 n, 16 m) = 128 co-resident CTAs (1/SM).
// C tile [m0:m0+128) x [n0:n0+64) per CTA for the whole sequence.
// Wh1/Wh2 n-slices resident in smem; m-group sync via monotonic atomics.
// ---------------------------------------------------------------------------
__global__ void __launch_bounds__(256)
rnn_persistent(const int* __restrict__ tokens,
               const float* __restrict__ b1, const float* __restrict__ b2)
{
    extern __shared__ __align__(1024) char smem[];
    const uint32_t sb = smem_u32(smem);
    const int tid = threadIdx.x, wid = tid >> 5, lane = tid & 31;
    const int n0 = blockIdx.x * 64, m0 = blockIdx.y * 128;
    const int grp = blockIdx.y;

    // warp layout: 4 m-warps x 2 n-warps; warp tile 32x32
    const int wm = (wid & 3) * 32;
    const int wn = (wid >> 2) * 32;
    const int sel = lane >> 3, rowin = lane & 7;
    const int a_row  = wm + (sel & 1) * 8 + rowin;
    const int a_colb = (sel >> 1) * 16;
    const int b_row  = wn + (sel >> 1) * 8 + rowin;
    const int b_colb = (sel & 1) * 16;
    const int grpq = lane >> 2, qd = (lane & 3) * 2;

    // ---- one-time: load resident Wh1, Wh2 n-slices (8 x 8KB K-64 halves) ----
    #pragma unroll
    for (int m = 0; m < 2; ++m) {
        const __half* src = g_W[m ? 4 : 2];                 // Wh1, Wh2
        const uint32_t base = sb + WH_OFF + (uint32_t)m * 65536u;
        #pragma unroll
        for (int hh = 0; hh < 8; ++hh)
            #pragma unroll
            for (int i = 0; i < 2; ++i) {
                int idx = tid + i * 256;
                int row = idx >> 3, g = idx & 7;
                uint32_t d = swz((uint32_t)(row * 128 + g * 16));
                CP16(base + hh * 8192u + d,
                     src + (size_t)(n0 + row) * UNITS + hh * 64 + g * 8);
            }
    }
    asm volatile("cp.async.commit_group;" ::: "memory");
    asm volatile("cp.async.wait_group 0;" ::: "memory");
    __syncthreads();

    int bidx = 0;   // barrier instance counter (uniform across threads)

    for (int t = 0; t < SEQ; ++t) {
        const int p = t & 1;
        #pragma unroll 1
        for (int layer = 0; layer < 3; ++layer) {
            // chunk plan:
            //   layer 0 : NC=4, chunks 0-3: A=s0(t-1), B=Wh0 staged
            //   layer1/2: NC=8, chunks 0-3: A=o_{l-1}(t), B=Wx staged
            //                   chunks 4-7: A=s_l(t-1), B=resident Wh_l
            const __half *Ax, *As_, *Bx;
            uint32_t whb = 0;
            const float* bias = nullptr;
            int NC;
            if (layer == 0) {
                NC = 4;
                Ax = g_s[0][p];  As_ = Ax;  Bx = g_W[0];
            } else {
                NC = 8;
                Ax  = g_s[layer - 1][p ^ 1];
                As_ = g_s[layer][p];
                Bx  = g_W[layer == 1 ? 1 : 3];
                whb = sb + WH_OFF + (uint32_t)(layer - 1) * 65536u;
                bias = (layer == 1) ? b1 : b2;
            }
            __half* outp = g_s[layer][p ^ 1];

            float acc[2][4][4] = {};

            // depth-1 double buffer: prime chunk 0
            load_chunk(sb, (layer == 0 || 0 < 4) ? Ax : As_,
                       Bx, 0, m0, n0, tid);

            for (int c = 0; c < NC; ++c) {
                asm volatile("cp.async.wait_group 0;" ::: "memory");
                __syncthreads();

                const int nc = c + 1;
                if (nc < NC) {
                    const bool xch = (layer == 0) || (nc < 4);
                    load_chunk(sb + (uint32_t)(nc & 1) * STAGE,
                               xch ? Ax : As_,
                               xch ? Bx : nullptr,
                               (nc & 3) * 128, m0, n0, tid);
                }

                const uint32_t stg = sb + (uint32_t)(c & 1) * STAGE;
                const bool cres = (layer > 0) && (c >= 4);   // resident B
                #pragma unroll
                for (int h = 0; h < 2; ++h) {
                    const uint32_t Ab = stg + h * 16384u;
                    const uint32_t Bb = cres
                        ? (whb + (uint32_t)(((c & 3) * 2 + h)) * 8192u)
                        : (stg + 32768u + h * 8192u);
                    #pragma unroll
                    for (int ks = 0; ks < 4; ++ks) {
                        uint32_t a[2][4], b[2][4];
                        #pragma unroll
                        for (int mt = 0; mt < 2; ++mt) {
                            uint32_t off = swz((uint32_t)((a_row + mt * 16) * 128 + a_colb + ks * 32));
                            ldsm4(a[mt], Ab + off);
                        }
                        #pragma unroll
                        for (int bt = 0; bt < 2; ++bt) {
                            uint32_t off = swz((uint32_t)((b_row + bt * 16) * 128 + b_colb + ks * 32));
                            ldsm4(b[bt], Bb + off);
                        }
                        #pragma unroll
                        for (int mt = 0; mt < 2; ++mt)
                            #pragma unroll
                            for (int j = 0; j < 4; ++j)
                                mma16816(acc[mt][j], a[mt], &b[j >> 1][(j & 1) * 2]);
                    }
                }
            }

            // ---- epilogue: add T/bias, tanh, fp16 store ----
            #pragma unroll
            for (int mt = 0; mt < 2; ++mt) {
                const int r0 = m0 + wm + mt * 16 + grpq;
                const int r1 = r0 + 8;
                const float *t0, *t1;
                if (layer == 0) {
                    t0 = g_T + (size_t)tokens[(size_t)r0 * SEQ + t] * UNITS;
                    t1 = g_T + (size_t)tokens[(size_t)r1 * SEQ + t] * UNITS;
                } else {
                    t0 = bias; t1 = bias;
                }
                #pragma unroll
                for (int j = 0; j < 4; ++j) {
                    const int c = n0 + wn + j * 8 + qd;
                    float2 ad0 = *(const float2*)(t0 + c);
                    float2 ad1 = *(const float2*)(t1 + c);
                    __half2 p0 = __floats2half2_rn(fast_tanh(acc[mt][j][0] + ad0.x),
                                                   fast_tanh(acc[mt][j][1] + ad0.y));
                    __half2 p1 = __floats2half2_rn(fast_tanh(acc[mt][j][2] + ad1.x),
                                                   fast_tanh(acc[mt][j][3] + ad1.y));
                    *reinterpret_cast<__half2*>(outp + (size_t)r0 * UNITS + c) = p0;
                    *reinterpret_cast<__half2*>(outp + (size_t)r1 * UNITS + c) = p1;
                }
            }

            // ---- m-group barrier (8 CTAs), monotonic counter ----
            ++bidx;
            __syncthreads();
            if (tid == 0) {
                __threadfence();
                atomicAdd(&g_bar[grp], 1);
                const int target = 8 * bidx;
                unsigned ns = 8;
                for (;;) {
                    int v;
                    asm volatile("ld.acquire.gpu.s32 %0, [%1];"
                                 : "=r"(v) : "l"(&g_bar[grp]));
                    if (v >= target) break;
                    __nanosleep(ns);
                    if (ns < 128) ns <<= 1;
                }
            }
            __syncthreads();
        }
    }
}

// ---------------------------------------------------------------------------
// head: out[b] = sigmoid( s2[b,:] . Wout + bout )
// ---------------------------------------------------------------------------
__global__ void __launch_bounds__(256)
head_kernel(const float* __restrict__ Wout, const float* __restrict__ bout,
            float* __restrict__ out)
{
    const __half* s2 = g_s[2][0];   // SEQ even -> final state in phase 0
    int row  = blockIdx.x * 8 + (threadIdx.x >> 5);
    int lane = threadIdx.x & 31;
    float sum = 0.0f;
    #pragma unroll 4
    for (int k = lane; k < UNITS; k += 32)
        sum += __half2float(s2[(size_t)row * UNITS + k]) * Wout[k];
    #pragma unroll
    for (int o = 16; o; o >>= 1)
        sum += __shfl_xor_sync(0xFFFFFFFFu, sum, o);
    if (lane == 0) {
        float logit = sum + bout[0];
        out[row] = __fdividef(1.0f, 1.0f + __expf(-logit));
    }
}

// ---------------------------------------------------------------------------
extern "C" void kernel_launch(void* const* d_in, const int* in_sizes, int n_in,
                              void* d_out, int out_size)
{
    const int*   tokens = (const int*)  d_in[0];
    const float* emb    = (const float*)d_in[1];
    const float* Wx0    = (const float*)d_in[2];
    const float* Wh0    = (const float*)d_in[3];
    const float* b0     = (const float*)d_in[4];
    const float* Wx1    = (const float*)d_in[5];
    const float* Wh1    = (const float*)d_in[6];
    const float* b1     = (const float*)d_in[7];
    const float* Wx2    = (const float*)d_in[8];
    const float* Wh2    = (const float*)d_in[9];
    const float* b2     = (const float*)d_in[10];
    const float* Wout   = (const float*)d_in[11];
    const float* bout   = (const float*)d_in[12];
    float* out = (float*)d_out;

    cudaFuncSetAttribute(rnn_persistent, cudaFuncAttributeMaxDynamicSharedMemorySize,
                         SMEM_BYTES);

    // prologue
    xproj_kernel<<<dim3((VOCAB + 63) / 64, UNITS / 64), 256>>>(emb, Wx0, b0);
    conv_weights<<<(UNITS * UNITS) / 256, 256>>>(Wh0, Wx1, Wh1, Wx2, Wh2);
    init_states<<<(BATCH * UNITS) / 256, 256>>>();

    // the whole 80x3 recurrence in one persistent launch
    dim3 grid(UNITS / 64, BATCH / 128);   // (8 n, 16 m) = 128 CTAs, 1/SM
    rnn_persistent<<<grid, 256, SMEM_BYTES>>>(tokens, b1, b2);

    head_kernel<<<BATCH / 8, 256>>>(Wout, bout, out);
}

// round 10
// speedup vs baseline: 1.2586x; 1.1281x over previous
#include <cuda_runtime.h>
#include <cuda_fp16.h>
#include <stdint.h>
#include <math.h>

#define BATCH 2048
#define SEQ   80
#define EMBED 100
#define UNITS 512
#define VOCAB 10000

// ---------------- device globals (no allocation allowed) ----------------
__device__ float g_T[VOCAB * UNITS];            // emb@Wx0+b0 table (fp32, exact)
__device__ __half g_s[3][2][BATCH * UNITS];     // [layer][phase] fp16 states
__device__ __half g_W[5][UNITS * UNITS];        // transposed fp16 weights [n][k]:
                                                // 0=Wh0 1=Wx1 2=Wh1 3=Wx2 4=Wh2
__device__ int g_bar[16];                       // per-m-group monotonic barriers

// ---------------- helpers ----------------
__device__ __forceinline__ uint32_t smem_u32(const void* p) {
    uint32_t a;
    asm("{ .reg .u64 t; cvta.to.shared.u64 t, %1; cvt.u32.u64 %0, t; }" : "=r"(a) : "l"(p));
    return a;
}

__device__ __forceinline__ uint32_t swz(uint32_t off) {
    return off ^ ((off >> 3) & 0x70);   // SW128: 8-row period, 16B granules
}

#define CP16(dst, src) \
    asm volatile("cp.async.cg.shared.global [%0], [%1], 16;" :: "r"(dst), "l"(src) : "memory")

__device__ __forceinline__ void ldsm4(uint32_t (&r)[4], uint32_t addr) {
    asm volatile("ldmatrix.sync.aligned.m8n8.x4.shared.b16 {%0,%1,%2,%3}, [%4];"
        : "=r"(r[0]), "=r"(r[1]), "=r"(r[2]), "=r"(r[3]) : "r"(addr));
}

__device__ __forceinline__ void mma16816(float (&d)[4], const uint32_t (&a)[4],
                                         const uint32_t* b) {
    asm volatile(
        "mma.sync.aligned.m16n8k16.row.col.f32.f16.f16.f32 "
        "{%0,%1,%2,%3}, {%4,%5,%6,%7}, {%8,%9}, {%0,%1,%2,%3};"
        : "+f"(d[0]), "+f"(d[1]), "+f"(d[2]), "+f"(d[3])
        : "r"(a[0]), "r"(a[1]), "r"(a[2]), "r"(a[3]), "r"(b[0]), "r"(b[1]));
}

__device__ __forceinline__ float fast_tanh(float x) {
    float e = __expf(2.0f * x);
    return 1.0f - __fdividef(2.0f, e + 1.0f);
}

// Stage = one K-128 chunk: A(128x128) two 16K halves + B(64x128) two 8K halves
#define STAGE 49152u
#define NSTAGE 3
#define SMEM_BYTES (NSTAGE * STAGE)

// ---------------------------------------------------------------------------
// xproj: g_T = emb @ Wx0 + b0   (fp32, M=10000 K=100 N=512)
// ---------------------------------------------------------------------------
__global__ void __launch_bounds__(256)
xproj_kernel(const float* __restrict__ emb, const float* __restrict__ Wx0,
             const float* __restrict__ b0)
{
    __shared__ float As[20][68];
    __shared__ float Bs[20][68];
    const int m0 = blockIdx.x * 64, n0 = blockIdx.y * 64;
    const int tid = threadIdx.x, tx = tid & 15, ty = tid >> 4;
    float acc[4][4] = {};
    for (int k0 = 0; k0 < EMBED; k0 += 20) {
        for (int i = tid; i < 64 * 20; i += 256) {
            int m = i / 20, k = i % 20;
            int gm = m0 + m;
            As[k][m] = (gm < VOCAB) ? emb[gm * EMBED + k0 + k] : 0.0f;
        }
        for (int i = tid; i < 20 * 64; i += 256) {
            int k = i / 64, n = i % 64;
            Bs[k][n] = Wx0[(k0 + k) * UNITS + n0 + n];
        }
        __syncthreads();
        #pragma unroll
        for (int kk = 0; kk < 20; ++kk) {
            float a[4], b[4];
            #pragma unroll
            for (int i = 0; i < 4; ++i) a[i] = As[kk][ty * 4 + i];
            #pragma unroll
            for (int j = 0; j < 4; ++j) b[j] = Bs[kk][tx * 4 + j];
            #pragma unroll
            for (int i = 0; i < 4; ++i)
                #pragma unroll
                for (int j = 0; j < 4; ++j)
                    acc[i][j] = fmaf(a[i], b[j], acc[i][j]);
        }
        __syncthreads();
    }
    #pragma unroll
    for (int i = 0; i < 4; ++i) {
        int row = m0 + ty * 4 + i;
        if (row >= VOCAB) continue;
        #pragma unroll
        for (int j = 0; j < 4; ++j) {
            int col = n0 + tx * 4 + j;
            g_T[row * UNITS + col] = acc[i][j] + b0[col];
        }
    }
}

// ---------------------------------------------------------------------------
// transpose + convert weights: g_W[m][n*512+k] = fp16(W[k*512+n])
// ---------------------------------------------------------------------------
__global__ void __launch_bounds__(256)
conv_weights(const float* __restrict__ a0, const float* __restrict__ a1,
             const float* __restrict__ a2, const float* __restrict__ a3,
             const float* __restrict__ a4)
{
    int i = blockIdx.x * 256 + threadIdx.x;   // i = k*512+n
    int k = i >> 9, n = i & 511;
    const float* src[5] = {a0, a1, a2, a3, a4};
    #pragma unroll
    for (int m = 0; m < 5; ++m)
        g_W[m][n * UNITS + k] = __float2half_rn(src[m][i]);
}

__global__ void init_states()
{
    int i = blockIdx.x * blockDim.x + threadIdx.x;
    const __half z = __float2half(0.0f);
    #pragma unroll
    for (int l = 0; l < 3; ++l)
        g_s[l][0][i] = z;
    if (i < 16) g_bar[i] = 0;   // reset barriers on every launch/replay
}

// ---------------------------------------------------------------------------
// stage loader: A (128 x 128) + B (64 x 128) fp16, two 64-col halves each,
// SW128 swizzled 128B rows. One commit_group per stage.
// ---------------------------------------------------------------------------
__device__ __forceinline__ void load_stage(uint32_t base,
    const __half* __restrict__ A, const __half* __restrict__ B,
    int m0, int n0, int k0, int tid)
{
    #pragma unroll
    for (int h = 0; h < 2; ++h) {
        const int kh = k0 + h * 64;
        const uint32_t ab = base + h * 16384u;
        const uint32_t bb = base + 32768u + h * 8192u;
        #pragma unroll
        for (int i = 0; i < 4; ++i) {           // A half: 1024 x 16B
            int idx = tid + i * 256;
            int row = idx >> 3, g = idx & 7;
            uint32_t d = swz((uint32_t)(row * 128 + g * 16));
            CP16(ab + d, A + (size_t)(m0 + row) * UNITS + kh + g * 8);
        }
        #pragma unroll
        for (int i = 0; i < 2; ++i) {           // B half: 512 x 16B
            int idx = tid + i * 256;
            int row = idx >> 3, g = idx & 7;
            uint32_t d = swz((uint32_t)(row * 128 + g * 16));
            CP16(bb + d, B + (size_t)(n0 + row) * UNITS + kh + g * 8);
        }
    }
    asm volatile("cp.async.commit_group;" ::: "memory");
}

// ---------------------------------------------------------------------------
// persistent RNN: grid (8 n, 16 m) = 128 co-resident CTAs (1/SM).
// Per layer: signal(prev) -> prime 2 chunks of OLD-data half -> barrier wait
// (hidden under primes) -> pipelined mainloop -> epilogue.
// Chunk order (layers 1/2): 0-3 Wh-half (s_l(t-1)@Wh_l), 4-7 Wx-half
// (o_{l-1}(t)@Wx_l).  All primed data is guaranteed by the PREVIOUS layer's
// barrier wait; fresh data is first touched after this layer's wait.
// ---------------------------------------------------------------------------
__global__ void __launch_bounds__(256)
rnn_persistent(const int* __restrict__ tokens,
               const float* __restrict__ b1, const float* __restrict__ b2)
{
    extern __shared__ __align__(1024) char smem[];
    const uint32_t sb = smem_u32(smem);
    const int tid = threadIdx.x, wid = tid >> 5, lane = tid & 31;
    const int n0 = blockIdx.x * 64, m0 = blockIdx.y * 128;
    const int grp = blockIdx.y;

    // warp layout: 4 m-warps x 2 n-warps; warp tile 32x32
    const int wm = (wid & 3) * 32;
    const int wn = (wid >> 2) * 32;
    const int sel = lane >> 3, rowin = lane & 7;
    const int a_row  = wm + (sel & 1) * 8 + rowin;
    const int a_colb = (sel >> 1) * 16;
    const int b_row  = wn + (sel >> 1) * 8 + rowin;
    const int b_colb = (sel & 1) * 16;
    const int grpq = lane >> 2, qd = (lane & 3) * 2;

    int bidx = 0;   // completed (t,layer) instances group-wide (uniform)

    for (int t = 0; t < SEQ; ++t) {
        const int p = t & 1;
        #pragma unroll 1
        for (int layer = 0; layer < 3; ++layer) {
            const __half *A0, *B0, *A1, *B1;
            int nmat;
            const float* bias;
            if (layer == 0) {
                nmat = 1; bias = nullptr;
                A0 = g_s[0][p];  B0 = g_W[0];      // s0(t-1) @ Wh0  (old data)
                A1 = A0;         B1 = B0;
            } else {
                nmat = 2;
                int wx = (layer == 1) ? 1 : 3;
                bias = (layer == 1) ? b1 : b2;
                A0 = g_s[layer][p];          B0 = g_W[wx + 1];  // Wh half (old)
                A1 = g_s[layer - 1][p ^ 1];  B1 = g_W[wx];      // Wx half (fresh)
            }
            __half* outp = g_s[layer][p ^ 1];
            const __half* Asrc[2] = {A0, A1};
            const __half* Bsrc[2] = {B0, B1};
            const int NC = nmat * 4;   // K-128 stages

            // ---- prime chunks 0,1 (old data only) BEFORE the barrier wait ----
            load_stage(sb + 0 * STAGE, A0, B0, m0, n0, 0, tid);
            load_stage(sb + 1 * STAGE, A0, B0, m0, n0, 128, tid);

            // ---- barrier: all group CTAs done with previous (t,layer) ----
            if (tid == 0) {
                const int target = 8 * bidx;
                unsigned ns = 8;
                for (;;) {
                    int v;
                    asm volatile("ld.acquire.gpu.s32 %0, [%1];"
                                 : "=r"(v) : "l"(&g_bar[grp]));
                    if (v >= target) break;
                    __nanosleep(ns);
                    if (ns < 128) ns <<= 1;
                }
            }
            __syncthreads();

            float acc[2][4][4] = {};

            for (int c = 0; c < NC; ++c) {
                asm volatile("cp.async.wait_group 1;" ::: "memory");
                __syncthreads();

                const int nc = c + 2;
                if (nc < NC) {
                    load_stage(sb + (nc % NSTAGE) * STAGE,
                               Asrc[nc >> 2], Bsrc[nc >> 2],
                               m0, n0, (nc & 3) * 128, tid);
                } else {
                    asm volatile("cp.async.commit_group;" ::: "memory");
                }

                const uint32_t stb = sb + (uint32_t)(c % NSTAGE) * STAGE;
                #pragma unroll
                for (int h = 0; h < 2; ++h) {
                    const uint32_t Ab = stb + h * 16384u;
                    const uint32_t Bb = stb + 32768u + h * 8192u;
                    #pragma unroll
                    for (int ks = 0; ks < 4; ++ks) {
                        uint32_t a[2][4], b[2][4];
                        #pragma unroll
                        for (int mt = 0; mt < 2; ++mt) {
                            uint32_t off = swz((uint32_t)((a_row + mt * 16) * 128 + a_colb + ks * 32));
                            ldsm4(a[mt], Ab + off);
                        }
                        #pragma unroll
                        for (int bt = 0; bt < 2; ++bt) {
                            uint32_t off = swz((uint32_t)((b_row + bt * 16) * 128 + b_colb + ks * 32));
                            ldsm4(b[bt], Bb + off);
                        }
                        #pragma unroll
                        for (int mt = 0; mt < 2; ++mt)
                            #pragma unroll
                            for (int j = 0; j < 4; ++j)
                                mma16816(acc[mt][j], a[mt], &b[j >> 1][(j & 1) * 2]);
                    }
                }
            }

            // ---- epilogue: add T/bias, tanh, fp16 store ----
            #pragma unroll
            for (int mt = 0; mt < 2; ++mt) {
                const int r0 = m0 + wm + mt * 16 + grpq;
                const int r1 = r0 + 8;
                const float *t0, *t1;
                if (layer == 0) {
                    t0 = g_T + (size_t)tokens[(size_t)r0 * SEQ + t] * UNITS;
                    t1 = g_T + (size_t)tokens[(size_t)r1 * SEQ + t] * UNITS;
                } else {
                    t0 = bias; t1 = bias;
                }
                #pragma unroll
                for (int j = 0; j < 4; ++j) {
                    const int c = n0 + wn + j * 8 + qd;
                    float2 ad0 = *(const float2*)(t0 + c);
                    float2 ad1 = *(const float2*)(t1 + c);
                    __half2 p0 = __floats2half2_rn(fast_tanh(acc[mt][j][0] + ad0.x),
                                                   fast_tanh(acc[mt][j][1] + ad0.y));
                    __half2 p1 = __floats2half2_rn(fast_tanh(acc[mt][j][2] + ad1.x),
                                                   fast_tanh(acc[mt][j][3] + ad1.y));
                    *reinterpret_cast<__half2*>(outp + (size_t)r0 * UNITS + c) = p0;
                    *reinterpret_cast<__half2*>(outp + (size_t)r1 * UNITS + c) = p1;
                }
            }

            // ---- signal completion; also fences smem stage reuse for primes ----
            __syncthreads();
            if (tid == 0) {
                __threadfence();
                atomicAdd(&g_bar[grp], 1);
            }
            ++bidx;
        }
    }
}

// ---------------------------------------------------------------------------
// head: out[b] = sigmoid( s2[b,:] . Wout + bout )
// ---------------------------------------------------------------------------
__global__ void __launch_bounds__(256)
head_kernel(const float* __restrict__ Wout, const float* __restrict__ bout,
            float* __restrict__ out)
{
    const __half* s2 = g_s[2][0];   // SEQ even -> final state in phase 0
    int row  = blockIdx.x * 8 + (threadIdx.x >> 5);
    int lane = threadIdx.x & 31;
    float sum = 0.0f;
    #pragma unroll 4
    for (int k = lane; k < UNITS; k += 32)
        sum += __half2float(s2[(size_t)row * UNITS + k]) * Wout[k];
    #pragma unroll
    for (int o = 16; o; o >>= 1)
        sum += __shfl_xor_sync(0xFFFFFFFFu, sum, o);
    if (lane == 0) {
        float logit = sum + bout[0];
        out[row] = __fdividef(1.0f, 1.0f + __expf(-logit));
    }
}

// ---------------------------------------------------------------------------
extern "C" void kernel_launch(void* const* d_in, const int* in_sizes, int n_in,
                              void* d_out, int out_size)
{
    const int*   tokens = (const int*)  d_in[0];
    const float* emb    = (const float*)d_in[1];
    const float* Wx0    = (const float*)d_in[2];
    const float* Wh0    = (const float*)d_in[3];
    const float* b0     = (const float*)d_in[4];
    const float* Wx1    = (const float*)d_in[5];
    const float* Wh1    = (const float*)d_in[6];
    const float* b1     = (const float*)d_in[7];
    const float* Wx2    = (const float*)d_in[8];
    const float* Wh2    = (const float*)d_in[9];
    const float* b2     = (const float*)d_in[10];
    const float* Wout   = (const float*)d_in[11];
    const float* bout   = (const float*)d_in[12];
    float* out = (float*)d_out;

    cudaFuncSetAttribute(rnn_persistent, cudaFuncAttributeMaxDynamicSharedMemorySize,
                         SMEM_BYTES);

    // prologue
    xproj_kernel<<<dim3((VOCAB + 63) / 64, UNITS / 64), 256>>>(emb, Wx0, b0);
    conv_weights<<<(UNITS * UNITS) / 256, 256>>>(Wh0, Wx1, Wh1, Wx2, Wh2);
    init_states<<<(BATCH * UNITS) / 256, 256>>>();

    // the whole 80x3 recurrence in one persistent launch
    dim3 grid(UNITS / 64, BATCH / 128);   // (8 n, 16 m) = 128 CTAs, 1/SM
    rnn_persistent<<<grid, 256, SMEM_BYTES>>>(tokens, b1, b2);

    head_kernel<<<BATCH / 8, 256>>>(Wout, bout, out);
}

// round 11
// speedup vs baseline: 1.2590x; 1.0003x over previous
#include <cuda_runtime.h>
#include <cuda_fp16.h>
#include <stdint.h>
#include <math.h>

#define BATCH 2048
#define SEQ   80
#define EMBED 100
#define UNITS 512
#define VOCAB 10000

// ---------------- device globals (no allocation allowed) ----------------
__device__ float g_T[VOCAB * UNITS];            // emb@Wx0+b0 table (fp32, exact)
__device__ __half g_s[3][2][BATCH * UNITS];     // [layer][phase] fp16 states
__device__ __half g_W[5][UNITS * UNITS];        // transposed fp16 weights [n][k]:
                                                // 0=Wh0 1=Wx1 2=Wh1 3=Wx2 4=Wh2
__device__ int g_bar[16];                       // per-m-group monotonic barriers

// ---------------- helpers ----------------
__device__ __forceinline__ uint32_t smem_u32(const void* p) {
    uint32_t a;
    asm("{ .reg .u64 t; cvta.to.shared.u64 t, %1; cvt.u32.u64 %0, t; }" : "=r"(a) : "l"(p));
    return a;
}

__device__ __forceinline__ uint32_t swz(uint32_t off) {
    return off ^ ((off >> 3) & 0x70);   // SW128: 8-row period, 16B granules
}

#define CP16(dst, src) \
    asm volatile("cp.async.cg.shared.global [%0], [%1], 16;" :: "r"(dst), "l"(src) : "memory")

__device__ __forceinline__ void ldsm4(uint32_t (&r)[4], uint32_t addr) {
    asm volatile("ldmatrix.sync.aligned.m8n8.x4.shared.b16 {%0,%1,%2,%3}, [%4];"
        : "=r"(r[0]), "=r"(r[1]), "=r"(r[2]), "=r"(r[3]) : "r"(addr));
}

__device__ __forceinline__ void mma16816(float (&d)[4], const uint32_t (&a)[4],
                                         const uint32_t* b) {
    asm volatile(
        "mma.sync.aligned.m16n8k16.row.col.f32.f16.f16.f32 "
        "{%0,%1,%2,%3}, {%4,%5,%6,%7}, {%8,%9}, {%0,%1,%2,%3};"
        : "+f"(d[0]), "+f"(d[1]), "+f"(d[2]), "+f"(d[3])
        : "r"(a[0]), "r"(a[1]), "r"(a[2]), "r"(a[3]), "r"(b[0]), "r"(b[1]));
}

__device__ __forceinline__ float fast_tanh(float x) {
    float e = __expf(2.0f * x);
    return 1.0f - __fdividef(2.0f, e + 1.0f);
}

// Stage = one K-128 chunk: A(128x128) two 16K halves + B(64x128) two 8K halves
#define STAGE 49152u
#define NSTAGE 3
#define SMEM_BYTES (NSTAGE * STAGE)

// ---------------------------------------------------------------------------
// xproj: g_T = emb @ Wx0 + b0   (fp32, M=10000 K=100 N=512)
// ---------------------------------------------------------------------------
__global__ void __launch_bounds__(256)
xproj_kernel(const float* __restrict__ emb, const float* __restrict__ Wx0,
             const float* __restrict__ b0)
{
    __shared__ float As[20][68];
    __shared__ float Bs[20][68];
    const int m0 = blockIdx.x * 64, n0 = blockIdx.y * 64;
    const int tid = threadIdx.x, tx = tid & 15, ty = tid >> 4;
    float acc[4][4] = {};
    for (int k0 = 0; k0 < EMBED; k0 += 20) {
        for (int i = tid; i < 64 * 20; i += 256) {
            int m = i / 20, k = i % 20;
            int gm = m0 + m;
            As[k][m] = (gm < VOCAB) ? emb[gm * EMBED + k0 + k] : 0.0f;
        }
        for (int i = tid; i < 20 * 64; i += 256) {
            int k = i / 64, n = i % 64;
            Bs[k][n] = Wx0[(k0 + k) * UNITS + n0 + n];
        }
        __syncthreads();
        #pragma unroll
        for (int kk = 0; kk < 20; ++kk) {
            float a[4], b[4];
            #pragma unroll
            for (int i = 0; i < 4; ++i) a[i] = As[kk][ty * 4 + i];
            #pragma unroll
            for (int j = 0; j < 4; ++j) b[j] = Bs[kk][tx * 4 + j];
            #pragma unroll
            for (int i = 0; i < 4; ++i)
                #pragma unroll
                for (int j = 0; j < 4; ++j)
                    acc[i][j] = fmaf(a[i], b[j], acc[i][j]);
        }
        __syncthreads();
    }
    #pragma unroll
    for (int i = 0; i < 4; ++i) {
        int row = m0 + ty * 4 + i;
        if (row >= VOCAB) continue;
        #pragma unroll
        for (int j = 0; j < 4; ++j) {
            int col = n0 + tx * 4 + j;
            g_T[row * UNITS + col] = acc[i][j] + b0[col];
        }
    }
}

// ---------------------------------------------------------------------------
// transpose + convert weights: g_W[m][n*512+k] = fp16(W[k*512+n])
// ---------------------------------------------------------------------------
__global__ void __launch_bounds__(256)
conv_weights(const float* __restrict__ a0, const float* __restrict__ a1,
             const float* __restrict__ a2, const float* __restrict__ a3,
             const float* __restrict__ a4)
{
    int i = blockIdx.x * 256 + threadIdx.x;   // i = k*512+n
    int k = i >> 9, n = i & 511;
    const float* src[5] = {a0, a1, a2, a3, a4};
    #pragma unroll
    for (int m = 0; m < 5; ++m)
        g_W[m][n * UNITS + k] = __float2half_rn(src[m][i]);
}

__global__ void init_states()
{
    int i = blockIdx.x * blockDim.x + threadIdx.x;
    const __half z = __float2half(0.0f);
    #pragma unroll
    for (int l = 0; l < 3; ++l)
        g_s[l][0][i] = z;
    if (i < 16) g_bar[i] = 0;   // reset barriers on every launch/replay
}

// ---------------------------------------------------------------------------
// stage loader: A (128 x 128) + B (64 x 128) fp16, two 64-col halves each,
// SW128 swizzled 128B rows. One commit_group per stage.
// ---------------------------------------------------------------------------
__device__ __forceinline__ void load_stage(uint32_t base,
    const __half* __restrict__ A, const __half* __restrict__ B,
    int m0, int n0, int k0, int tid)
{
    #pragma unroll
    for (int h = 0; h < 2; ++h) {
        const int kh = k0 + h * 64;
        const uint32_t ab = base + h * 16384u;
        const uint32_t bb = base + 32768u + h * 8192u;
        #pragma unroll
        for (int i = 0; i < 4; ++i) {           // A half: 1024 x 16B
            int idx = tid + i * 256;
            int row = idx >> 3, g = idx & 7;
            uint32_t d = swz((uint32_t)(row * 128 + g * 16));
            CP16(ab + d, A + (size_t)(m0 + row) * UNITS + kh + g * 8);
        }
        #pragma unroll
        for (int i = 0; i < 2; ++i) {           // B half: 512 x 16B
            int idx = tid + i * 256;
            int row = idx >> 3, g = idx & 7;
            uint32_t d = swz((uint32_t)(row * 128 + g * 16));
            CP16(bb + d, B + (size_t)(n0 + row) * UNITS + kh + g * 8);
        }
    }
    asm volatile("cp.async.commit_group;" ::: "memory");
}

// ---------------------------------------------------------------------------
// fragment loader: sub-iteration s in [0,8) = (h = s>>2, ks = s&3)
// ---------------------------------------------------------------------------
__device__ __forceinline__ void load_frag(uint32_t stb, int s,
    uint32_t (&fa)[2][4], uint32_t (&fb)[2][4],
    int a_row, int a_colb, int b_row, int b_colb)
{
    const int h = s >> 2, ks = s & 3;
    const uint32_t Ab = stb + (uint32_t)h * 16384u;
    const uint32_t Bb = stb + 32768u + (uint32_t)h * 8192u;
    #pragma unroll
    for (int mt = 0; mt < 2; ++mt) {
        uint32_t off = swz((uint32_t)((a_row + mt * 16) * 128 + a_colb + ks * 32));
        ldsm4(fa[mt], Ab + off);
    }
    #pragma unroll
    for (int bt = 0; bt < 2; ++bt) {
        uint32_t off = swz((uint32_t)((b_row + bt * 16) * 128 + b_colb + ks * 32));
        ldsm4(fb[bt], Bb + off);
    }
}

// ---------------------------------------------------------------------------
// persistent RNN: grid (8 n, 16 m) = 128 co-resident CTAs (1/SM).
// Per layer: prime 2 chunks of OLD-data half -> barrier wait (hidden under
// primes) -> pipelined mainloop with register double-buffered fragments.
// Chunk order (layers 1/2): 0-3 Wh-half (s_l(t-1)@Wh_l), 4-7 Wx-half
// (o_{l-1}(t)@Wx_l).
// ---------------------------------------------------------------------------
__global__ void __launch_bounds__(256, 1)
rnn_persistent(const int* __restrict__ tokens,
               const float* __restrict__ b1, const float* __restrict__ b2)
{
    extern __shared__ __align__(1024) char smem[];
    const uint32_t sb = smem_u32(smem);
    const int tid = threadIdx.x, wid = tid >> 5, lane = tid & 31;
    const int n0 = blockIdx.x * 64, m0 = blockIdx.y * 128;
    const int grp = blockIdx.y;

    // warp layout: 4 m-warps x 2 n-warps; warp tile 32x32
    const int wm = (wid & 3) * 32;
    const int wn = (wid >> 2) * 32;
    const int sel = lane >> 3, rowin = lane & 7;
    const int a_row  = wm + (sel & 1) * 8 + rowin;
    const int a_colb = (sel >> 1) * 16;
    const int b_row  = wn + (sel >> 1) * 8 + rowin;
    const int b_colb = (sel & 1) * 16;
    const int grpq = lane >> 2, qd = (lane & 3) * 2;

    int bidx = 0;   // completed (t,layer) instances group-wide (uniform)

    for (int t = 0; t < SEQ; ++t) {
        const int p = t & 1;
        #pragma unroll 1
        for (int layer = 0; layer < 3; ++layer) {
            const __half *A0, *B0, *A1, *B1;
            int nmat;
            const float* bias;
            if (layer == 0) {
                nmat = 1; bias = nullptr;
                A0 = g_s[0][p];  B0 = g_W[0];      // s0(t-1) @ Wh0  (old data)
                A1 = A0;         B1 = B0;
            } else {
                nmat = 2;
                int wx = (layer == 1) ? 1 : 3;
                bias = (layer == 1) ? b1 : b2;
                A0 = g_s[layer][p];          B0 = g_W[wx + 1];  // Wh half (old)
                A1 = g_s[layer - 1][p ^ 1];  B1 = g_W[wx];      // Wx half (fresh)
            }
            __half* outp = g_s[layer][p ^ 1];
            const __half* Asrc[2] = {A0, A1};
            const __half* Bsrc[2] = {B0, B1};
            const int NC = nmat * 4;   // K-128 stages

            // ---- prime chunks 0,1 (old data only) BEFORE the barrier wait ----
            load_stage(sb + 0 * STAGE, A0, B0, m0, n0, 0, tid);
            load_stage(sb + 1 * STAGE, A0, B0, m0, n0, 128, tid);

            // ---- barrier: all group CTAs done with previous (t,layer) ----
            if (tid == 0) {
                const int target = 8 * bidx;
                unsigned ns = 8;
                for (;;) {
                    int v;
                    asm volatile("ld.acquire.gpu.s32 %0, [%1];"
                                 : "=r"(v) : "l"(&g_bar[grp]));
                    if (v >= target) break;
                    __nanosleep(ns);
                    if (ns < 128) ns <<= 1;
                }
            }
            __syncthreads();

            float acc[2][4][4] = {};

            for (int c = 0; c < NC; ++c) {
                asm volatile("cp.async.wait_group 1;" ::: "memory");
                __syncthreads();

                const int nc = c + 2;
                if (nc < NC) {
                    load_stage(sb + (nc % NSTAGE) * STAGE,
                               Asrc[nc >> 2], Bsrc[nc >> 2],
                               m0, n0, (nc & 3) * 128, tid);
                } else {
                    asm volatile("cp.async.commit_group;" ::: "memory");
                }

                const uint32_t stb = sb + (uint32_t)(c % NSTAGE) * STAGE;

                // register double-buffered fragment pipeline over 8 sub-iters
                uint32_t fa[2][2][4], fb[2][2][4];
                load_frag(stb, 0, fa[0], fb[0], a_row, a_colb, b_row, b_colb);
                #pragma unroll
                for (int s = 0; s < 8; ++s) {
                    const int cur = s & 1;
                    if (s < 7)
                        load_frag(stb, s + 1, fa[cur ^ 1], fb[cur ^ 1],
                                  a_row, a_colb, b_row, b_colb);
                    #pragma unroll
                    for (int mt = 0; mt < 2; ++mt)
                        #pragma unroll
                        for (int j = 0; j < 4; ++j)
                            mma16816(acc[mt][j], fa[cur][mt],
                                     &fb[cur][j >> 1][(j & 1) * 2]);
                }
            }

            // ---- epilogue: add T/bias, tanh, fp16 store ----
            #pragma unroll
            for (int mt = 0; mt < 2; ++mt) {
                const int r0 = m0 + wm + mt * 16 + grpq;
                const int r1 = r0 + 8;
                const float *t0, *t1;
                if (layer == 0) {
                    t0 = g_T + (size_t)tokens[(size_t)r0 * SEQ + t] * UNITS;
                    t1 = g_T + (size_t)tokens[(size_t)r1 * SEQ + t] * UNITS;
                } else {
                    t0 = bias; t1 = bias;
                }
                #pragma unroll
                for (int j = 0; j < 4; ++j) {
                    const int c = n0 + wn + j * 8 + qd;
                    float2 ad0 = *(const float2*)(t0 + c);
                    float2 ad1 = *(const float2*)(t1 + c);
                    __half2 p0 = __floats2half2_rn(fast_tanh(acc[mt][j][0] + ad0.x),
                                                   fast_tanh(acc[mt][j][1] + ad0.y));
                    __half2 p1 = __floats2half2_rn(fast_tanh(acc[mt][j][2] + ad1.x),
                                                   fast_tanh(acc[mt][j][3] + ad1.y));
                    *reinterpret_cast<__half2*>(outp + (size_t)r0 * UNITS + c) = p0;
                    *reinterpret_cast<__half2*>(outp + (size_t)r1 * UNITS + c) = p1;
                }
            }

            // ---- signal completion ----
            __syncthreads();
            if (tid == 0) {
                __threadfence();
                atomicAdd(&g_bar[grp], 1);
            }
            ++bidx;
        }
    }
}

// ---------------------------------------------------------------------------
// head: out[b] = sigmoid( s2[b,:] . Wout + bout )
// ---------------------------------------------------------------------------
__global__ void __launch_bounds__(256)
head_kernel(const float* __restrict__ Wout, const float* __restrict__ bout,
            float* __restrict__ out)
{
    const __half* s2 = g_s[2][0];   // SEQ even -> final state in phase 0
    int row  = blockIdx.x * 8 + (threadIdx.x >> 5);
    int lane = threadIdx.x & 31;
    float sum = 0.0f;
    #pragma unroll 4
    for (int k = lane; k < UNITS; k += 32)
        sum += __half2float(s2[(size_t)row * UNITS + k]) * Wout[k];
    #pragma unroll
    for (int o = 16; o; o >>= 1)
        sum += __shfl_xor_sync(0xFFFFFFFFu, sum, o);
    if (lane == 0) {
        float logit = sum + bout[0];
        out[row] = __fdividef(1.0f, 1.0f + __expf(-logit));
    }
}

// ---------------------------------------------------------------------------
extern "C" void kernel_launch(void* const* d_in, const int* in_sizes, int n_in,
                              void* d_out, int out_size)
{
    const int*   tokens = (const int*)  d_in[0];
    const float* emb    = (const float*)d_in[1];
    const float* Wx0    = (const float*)d_in[2];
    const float* Wh0    = (const float*)d_in[3];
    const float* b0     = (const float*)d_in[4];
    const float* Wx1    = (const float*)d_in[5];
    const float* Wh1    = (const float*)d_in[6];
    const float* b1     = (const float*)d_in[7];
    const float* Wx2    = (const float*)d_in[8];
    const float* Wh2    = (const float*)d_in[9];
    const float* b2     = (const float*)d_in[10];
    const float* Wout   = (const float*)d_in[11];
    const float* bout   = (const float*)d_in[12];
    float* out = (float*)d_out;

    cudaFuncSetAttribute(rnn_persistent, cudaFuncAttributeMaxDynamicSharedMemorySize,
                         SMEM_BYTES);

    // prologue
    xproj_kernel<<<dim3((VOCAB + 63) / 64, UNITS / 64), 256>>>(emb, Wx0, b0);
    conv_weights<<<(UNITS * UNITS) / 256, 256>>>(Wh0, Wx1, Wh1, Wx2, Wh2);
    init_states<<<(BATCH * UNITS) / 256, 256>>>();

    // the whole 80x3 recurrence in one persistent launch
    dim3 grid(UNITS / 64, BATCH / 128);   // (8 n, 16 m) = 128 CTAs, 1/SM
    rnn_persistent<<<grid, 256, SMEM_BYTES>>>(tokens, b1, b2);

    head_kernel<<<BATCH / 8, 256>>>(Wout, bout, out);
}

// round 12
// speedup vs baseline: 1.3040x; 1.0358x over previous
#include <cuda_runtime.h>
#include <cuda_fp16.h>
#include <stdint.h>
#include <math.h>

#define BATCH 2048
#define SEQ   80
#define EMBED 100
#define UNITS 512
#define VOCAB 10000

// ---------------- device globals (no allocation allowed) ----------------
__device__ float g_T[VOCAB * UNITS];            // emb@Wx0+b0 table (fp32, exact)
__device__ __half g_s[3][2][BATCH * UNITS];     // [layer][phase] fp16 states
__device__ __half g_W[5][UNITS * UNITS];        // transposed fp16 weights [n][k]:
                                                // 0=Wh0 1=Wx1 2=Wh1 3=Wx2 4=Wh2
__device__ int g_bar[16];                       // per-m-group monotonic barriers

// ---------------- helpers ----------------
__device__ __forceinline__ uint32_t smem_u32(const void* p) {
    uint32_t a;
    asm("{ .reg .u64 t; cvta.to.shared.u64 t, %1; cvt.u32.u64 %0, t; }" : "=r"(a) : "l"(p));
    return a;
}

__device__ __forceinline__ uint32_t swz(uint32_t off) {
    return off ^ ((off >> 3) & 0x70);   // SW128: 8-row period, 16B granules
}

#define CP16(dst, src) \
    asm volatile("cp.async.cg.shared.global [%0], [%1], 16;" :: "r"(dst), "l"(src) : "memory")

__device__ __forceinline__ void ldsm4(uint32_t (&r)[4], uint32_t addr) {
    asm volatile("ldmatrix.sync.aligned.m8n8.x4.shared.b16 {%0,%1,%2,%3}, [%4];"
        : "=r"(r[0]), "=r"(r[1]), "=r"(r[2]), "=r"(r[3]) : "r"(addr));
}

__device__ __forceinline__ void mma16816(float (&d)[4], const uint32_t (&a)[4],
                                         const uint32_t* b) {
    asm volatile(
        "mma.sync.aligned.m16n8k16.row.col.f32.f16.f16.f32 "
        "{%0,%1,%2,%3}, {%4,%5,%6,%7}, {%8,%9}, {%0,%1,%2,%3};"
        : "+f"(d[0]), "+f"(d[1]), "+f"(d[2]), "+f"(d[3])
        : "r"(a[0]), "r"(a[1]), "r"(a[2]), "r"(a[3]), "r"(b[0]), "r"(b[1]));
}

// single-MUFU tanh (sm_75+ baseline PTX); abs err ~2^-11, same scale as the
// fp16 state rounding already in the recurrence.
__device__ __forceinline__ float fast_tanh(float x) {
    float y;
    asm("tanh.approx.f32 %0, %1;" : "=f"(y) : "f"(x));
    return y;
}

// Stage = one K-128 chunk: A(128x128) two 16K halves + B(64x128) two 8K halves
#define STAGE 49152u
#define NSTAGE 4
#define SMEM_BYTES (NSTAGE * STAGE)   // 196608 <= 227KB cap, 1 CTA/SM

// ---------------------------------------------------------------------------
// xproj: g_T = emb @ Wx0 + b0   (fp32, M=10000 K=100 N=512)
// ---------------------------------------------------------------------------
__global__ void __launch_bounds__(256)
xproj_kernel(const float* __restrict__ emb, const float* __restrict__ Wx0,
             const float* __restrict__ b0)
{
    __shared__ float As[20][68];
    __shared__ float Bs[20][68];
    const int m0 = blockIdx.x * 64, n0 = blockIdx.y * 64;
    const int tid = threadIdx.x, tx = tid & 15, ty = tid >> 4;
    float acc[4][4] = {};
    for (int k0 = 0; k0 < EMBED; k0 += 20) {
        for (int i = tid; i < 64 * 20; i += 256) {
            int m = i / 20, k = i % 20;
            int gm = m0 + m;
            As[k][m] = (gm < VOCAB) ? emb[gm * EMBED + k0 + k] : 0.0f;
        }
        for (int i = tid; i < 20 * 64; i += 256) {
            int k = i / 64, n = i % 64;
            Bs[k][n] = Wx0[(k0 + k) * UNITS + n0 + n];
        }
        __syncthreads();
        #pragma unroll
        for (int kk = 0; kk < 20; ++kk) {
            float a[4], b[4];
            #pragma unroll
            for (int i = 0; i < 4; ++i) a[i] = As[kk][ty * 4 + i];
            #pragma unroll
            for (int j = 0; j < 4; ++j) b[j] = Bs[kk][tx * 4 + j];
            #pragma unroll
            for (int i = 0; i < 4; ++i)
                #pragma unroll
                for (int j = 0; j < 4; ++j)
                    acc[i][j] = fmaf(a[i], b[j], acc[i][j]);
        }
        __syncthreads();
    }
    #pragma unroll
    for (int i = 0; i < 4; ++i) {
        int row = m0 + ty * 4 + i;
        if (row >= VOCAB) continue;
        #pragma unroll
        for (int j = 0; j < 4; ++j) {
            int col = n0 + tx * 4 + j;
            g_T[row * UNITS + col] = acc[i][j] + b0[col];
        }
    }
}

// ---------------------------------------------------------------------------
// transpose + convert weights: g_W[m][n*512+k] = fp16(W[k*512+n])
// ---------------------------------------------------------------------------
__global__ void __launch_bounds__(256)
conv_weights(const float* __restrict__ a0, const float* __restrict__ a1,
             const float* __restrict__ a2, const float* __restrict__ a3,
             const float* __restrict__ a4)
{
    int i = blockIdx.x * 256 + threadIdx.x;   // i = k*512+n
    int k = i >> 9, n = i & 511;
    const float* src[5] = {a0, a1, a2, a3, a4};
    #pragma unroll
    for (int m = 0; m < 5; ++m)
        g_W[m][n * UNITS + k] = __float2half_rn(src[m][i]);
}

__global__ void init_states()
{
    int i = blockIdx.x * blockDim.x + threadIdx.x;
    const __half z = __float2half(0.0f);
    #pragma unroll
    for (int l = 0; l < 3; ++l)
        g_s[l][0][i] = z;
    if (i < 16) g_bar[i] = 0;   // reset barriers on every launch/replay
}

// ---------------------------------------------------------------------------
// stage loader: A (128 x 128) + B (64 x 128) fp16, two 64-col halves each,
// SW128 swizzled 128B rows. One commit_group per stage.
// ---------------------------------------------------------------------------
__device__ __forceinline__ void load_stage(uint32_t base,
    const __half* __restrict__ A, const __half* __restrict__ B,
    int m0, int n0, int k0, int tid)
{
    #pragma unroll
    for (int h = 0; h < 2; ++h) {
        const int kh = k0 + h * 64;
        const uint32_t ab = base + h * 16384u;
        const uint32_t bb = base + 32768u + h * 8192u;
        #pragma unroll
        for (int i = 0; i < 4; ++i) {           // A half: 1024 x 16B
            int idx = tid + i * 256;
            int row = idx >> 3, g = idx & 7;
            uint32_t d = swz((uint32_t)(row * 128 + g * 16));
            CP16(ab + d, A + (size_t)(m0 + row) * UNITS + kh + g * 8);
        }
        #pragma unroll
        for (int i = 0; i < 2; ++i) {           // B half: 512 x 16B
            int idx = tid + i * 256;
            int row = idx >> 3, g = idx & 7;
            uint32_t d = swz((uint32_t)(row * 128 + g * 16));
            CP16(bb + d, B + (size_t)(n0 + row) * UNITS + kh + g * 8);
        }
    }
    asm volatile("cp.async.commit_group;" ::: "memory");
}

// ---------------------------------------------------------------------------
// fragment loader: sub-iteration s in [0,8) = (h = s>>2, ks = s&3)
// ---------------------------------------------------------------------------
__device__ __forceinline__ void load_frag(uint32_t stb, int s,
    uint32_t (&fa)[2][4], uint32_t (&fb)[2][4],
    int a_row, int a_colb, int b_row, int b_colb)
{
    const int h = s >> 2, ks = s & 3;
    const uint32_t Ab = stb + (uint32_t)h * 16384u;
    const uint32_t Bb = stb + 32768u + (uint32_t)h * 8192u;
    #pragma unroll
    for (int mt = 0; mt < 2; ++mt) {
        uint32_t off = swz((uint32_t)((a_row + mt * 16) * 128 + a_colb + ks * 32));
        ldsm4(fa[mt], Ab + off);
    }
    #pragma unroll
    for (int bt = 0; bt < 2; ++bt) {
        uint32_t off = swz((uint32_t)((b_row + bt * 16) * 128 + b_colb + ks * 32));
        ldsm4(fb[bt], Bb + off);
    }
}

// ---------------------------------------------------------------------------
// persistent RNN: grid (8 n, 16 m) = 128 co-resident CTAs (1/SM).
// Per layer: prime 3 chunks of OLD-data half -> barrier wait (hidden under
// primes) -> 4-deep pipelined mainloop (wait_group 2) -> MUFU.TANH epilogue.
// Chunk order (layers 1/2): 0-3 Wh-half (s_l(t-1)@Wh_l), 4-7 Wx-half
// (o_{l-1}(t)@Wx_l).  Primed chunks touch only old data; fresh data is
// first loaded after this layer's barrier wait.
// ---------------------------------------------------------------------------
__global__ void __launch_bounds__(256, 1)
rnn_persistent(const int* __restrict__ tokens,
               const float* __restrict__ b1, const float* __restrict__ b2)
{
    extern __shared__ __align__(1024) char smem[];
    const uint32_t sb = smem_u32(smem);
    const int tid = threadIdx.x, wid = tid >> 5, lane = tid & 31;
    const int n0 = blockIdx.x * 64, m0 = blockIdx.y * 128;
    const int grp = blockIdx.y;

    // warp layout: 4 m-warps x 2 n-warps; warp tile 32x32
    const int wm = (wid & 3) * 32;
    const int wn = (wid >> 2) * 32;
    const int sel = lane >> 3, rowin = lane & 7;
    const int a_row  = wm + (sel & 1) * 8 + rowin;
    const int a_colb = (sel >> 1) * 16;
    const int b_row  = wn + (sel >> 1) * 8 + rowin;
    const int b_colb = (sel & 1) * 16;
    const int grpq = lane >> 2, qd = (lane & 3) * 2;

    int bidx = 0;   // completed (t,layer) instances group-wide (uniform)

    for (int t = 0; t < SEQ; ++t) {
        const int p = t & 1;
        #pragma unroll 1
        for (int layer = 0; layer < 3; ++layer) {
            const __half *A0, *B0, *A1, *B1;
            int nmat;
            const float* bias;
            if (layer == 0) {
                nmat = 1; bias = nullptr;
                A0 = g_s[0][p];  B0 = g_W[0];      // s0(t-1) @ Wh0  (old data)
                A1 = A0;         B1 = B0;
            } else {
                nmat = 2;
                int wx = (layer == 1) ? 1 : 3;
                bias = (layer == 1) ? b1 : b2;
                A0 = g_s[layer][p];          B0 = g_W[wx + 1];  // Wh half (old)
                A1 = g_s[layer - 1][p ^ 1];  B1 = g_W[wx];      // Wx half (fresh)
            }
            __half* outp = g_s[layer][p ^ 1];
            const __half* Asrc[2] = {A0, A1};
            const __half* Bsrc[2] = {B0, B1};
            const int NC = nmat * 4;   // K-128 stages

            // ---- prime chunks 0,1,2 (old data only) BEFORE the barrier wait ----
            load_stage(sb + 0 * STAGE, A0, B0, m0, n0, 0, tid);
            load_stage(sb + 1 * STAGE, A0, B0, m0, n0, 128, tid);
            load_stage(sb + 2 * STAGE, A0, B0, m0, n0, 256, tid);

            // ---- barrier: all group CTAs done with previous (t,layer) ----
            if (tid == 0) {
                const int target = 8 * bidx;
                unsigned ns = 8;
                for (;;) {
                    int v;
                    asm volatile("ld.acquire.gpu.s32 %0, [%1];"
                                 : "=r"(v) : "l"(&g_bar[grp]));
                    if (v >= target) break;
                    __nanosleep(ns);
                    if (ns < 128) ns <<= 1;
                }
            }
            __syncthreads();

            float acc[2][4][4] = {};

            for (int c = 0; c < NC; ++c) {
                asm volatile("cp.async.wait_group 2;" ::: "memory");
                __syncthreads();

                const int nc = c + 3;
                if (nc < NC) {
                    load_stage(sb + (nc % NSTAGE) * STAGE,
                               Asrc[nc >> 2], Bsrc[nc >> 2],
                               m0, n0, (nc & 3) * 128, tid);
                } else {
                    asm volatile("cp.async.commit_group;" ::: "memory");
                }

                const uint32_t stb = sb + (uint32_t)(c % NSTAGE) * STAGE;

                // register double-buffered fragment pipeline over 8 sub-iters
                uint32_t fa[2][2][4], fb[2][2][4];
                load_frag(stb, 0, fa[0], fb[0], a_row, a_colb, b_row, b_colb);
                #pragma unroll
                for (int s = 0; s < 8; ++s) {
                    const int cur = s & 1;
                    if (s < 7)
                        load_frag(stb, s + 1, fa[cur ^ 1], fb[cur ^ 1],
                                  a_row, a_colb, b_row, b_colb);
                    #pragma unroll
                    for (int mt = 0; mt < 2; ++mt)
                        #pragma unroll
                        for (int j = 0; j < 4; ++j)
                            mma16816(acc[mt][j], fa[cur][mt],
                                     &fb[cur][j >> 1][(j & 1) * 2]);
                }
            }

            // ---- epilogue: add T/bias, MUFU tanh, fp16 store ----
            #pragma unroll
            for (int mt = 0; mt < 2; ++mt) {
                const int r0 = m0 + wm + mt * 16 + grpq;
                const int r1 = r0 + 8;
                const float *t0, *t1;
                if (layer == 0) {
                    t0 = g_T + (size_t)tokens[(size_t)r0 * SEQ + t] * UNITS;
                    t1 = g_T + (size_t)tokens[(size_t)r1 * SEQ + t] * UNITS;
                } else {
                    t0 = bias; t1 = bias;
                }
                #pragma unroll
                for (int j = 0; j < 4; ++j) {
                    const int c = n0 + wn + j * 8 + qd;
                    float2 ad0 = *(const float2*)(t0 + c);
                    float2 ad1 = *(const float2*)(t1 + c);
                    __half2 p0 = __floats2half2_rn(fast_tanh(acc[mt][j][0] + ad0.x),
                                                   fast_tanh(acc[mt][j][1] + ad0.y));
                    __half2 p1 = __floats2half2_rn(fast_tanh(acc[mt][j][2] + ad1.x),
                                                   fast_tanh(acc[mt][j][3] + ad1.y));
                    *reinterpret_cast<__half2*>(outp + (size_t)r0 * UNITS + c) = p0;
                    *reinterpret_cast<__half2*>(outp + (size_t)r1 * UNITS + c) = p1;
                }
            }

            // ---- signal completion ----
            __syncthreads();
            if (tid == 0) {
                __threadfence();
                atomicAdd(&g_bar[grp], 1);
            }
            ++bidx;
        }
    }
}

// ---------------------------------------------------------------------------
// head: out[b] = sigmoid( s2[b,:] . Wout + bout )
// ---------------------------------------------------------------------------
__global__ void __launch_bounds__(256)
head_kernel(const float* __restrict__ Wout, const float* __restrict__ bout,
            float* __restrict__ out)
{
    const __half* s2 = g_s[2][0];   // SEQ even -> final state in phase 0
    int row  = blockIdx.x * 8 + (threadIdx.x >> 5);
    int lane = threadIdx.x & 31;
    float sum = 0.0f;
    #pragma unroll 4
    for (int k = lane; k < UNITS; k += 32)
        sum += __half2float(s2[(size_t)row * UNITS + k]) * Wout[k];
    #pragma unroll
    for (int o = 16; o; o >>= 1)
        sum += __shfl_xor_sync(0xFFFFFFFFu, sum, o);
    if (lane == 0) {
        float logit = sum + bout[0];
        out[row] = __fdividef(1.0f, 1.0f + __expf(-logit));
    }
}

// ---------------------------------------------------------------------------
extern "C" void kernel_launch(void* const* d_in, const int* in_sizes, int n_in,
                              void* d_out, int out_size)
{
    const int*   tokens = (const int*)  d_in[0];
    const float* emb    = (const float*)d_in[1];
    const float* Wx0    = (const float*)d_in[2];
    const float* Wh0    = (const float*)d_in[3];
    const float* b0     = (const float*)d_in[4];
    const float* Wx1    = (const float*)d_in[5];
    const float* Wh1    = (const float*)d_in[6];
    const float* b1     = (const float*)d_in[7];
    const float* Wx2    = (const float*)d_in[8];
    const float* Wh2    = (const float*)d_in[9];
    const float* b2     = (const float*)d_in[10];
    const float* Wout   = (const float*)d_in[11];
    const float* bout   = (const float*)d_in[12];
    float* out = (float*)d_out;

    cudaFuncSetAttribute(rnn_persistent, cudaFuncAttributeMaxDynamicSharedMemorySize,
                         SMEM_BYTES);

    // prologue
    xproj_kernel<<<dim3((VOCAB + 63) / 64, UNITS / 64), 256>>>(emb, Wx0, b0);
    conv_weights<<<(UNITS * UNITS) / 256, 256>>>(Wh0, Wx1, Wh1, Wx2, Wh2);
    init_states<<<(BATCH * UNITS) / 256, 256>>>();

    // the whole 80x3 recurrence in one persistent launch
    dim3 grid(UNITS / 64, BATCH / 128);   // (8 n, 16 m) = 128 CTAs, 1/SM
    rnn_persistent<<<grid, 256, SMEM_BYTES>>>(tokens, b1, b2);

    head_kernel<<<BATCH / 8, 256>>>(Wout, bout, out);
}

// round 15
// speedup vs baseline: 1.3711x; 1.0514x over previous
#include <cuda_runtime.h>
#include <cuda_fp16.h>
#include <stdint.h>
#include <math.h>

#define BATCH 2048
#define SEQ   80
#define EMBED 100
#define UNITS 512
#define VOCAB 10000

// ---------------- device globals (no allocation allowed) ----------------
__device__ float g_T[VOCAB * UNITS];            // emb@Wx0+b0 table (fp32, exact)
__device__ __half g_s[3][2][BATCH * UNITS];     // [layer][phase] fp16 states
__device__ __half g_W[5][UNITS * UNITS];        // transposed fp16 weights [n][k]:
                                                // 0=Wh0 1=Wx1 2=Wh1 3=Wx2 4=Wh2
__device__ int g_bar[16];                       // per-m-group monotonic barriers

// ---------------- helpers ----------------
__device__ __forceinline__ uint32_t smem_u32(const void* p) {
    uint32_t a;
    asm("{ .reg .u64 t; cvta.to.shared.u64 t, %1; cvt.u32.u64 %0, t; }" : "=r"(a) : "l"(p));
    return a;
}

__device__ __forceinline__ uint32_t swz(uint32_t off) {
    return off ^ ((off >> 3) & 0x70);   // SW128: 8-row period, 16B granules
}

#define CP16(dst, src) \
    asm volatile("cp.async.cg.shared.global [%0], [%1], 16;" :: "r"(dst), "l"(src) : "memory")

__device__ __forceinline__ void ldsm4(uint32_t (&r)[4], uint32_t addr) {
    asm volatile("ldmatrix.sync.aligned.m8n8.x4.shared.b16 {%0,%1,%2,%3}, [%4];"
        : "=r"(r[0]), "=r"(r[1]), "=r"(r[2]), "=r"(r[3]) : "r"(addr));
}

__device__ __forceinline__ void mma16816(float (&d)[4], const uint32_t (&a)[4],
                                         const uint32_t* b) {
    asm volatile(
        "mma.sync.aligned.m16n8k16.row.col.f32.f16.f16.f32 "
        "{%0,%1,%2,%3}, {%4,%5,%6,%7}, {%8,%9}, {%0,%1,%2,%3};"
        : "+f"(d[0]), "+f"(d[1]), "+f"(d[2]), "+f"(d[3])
        : "r"(a[0]), "r"(a[1]), "r"(a[2]), "r"(a[3]), "r"(b[0]), "r"(b[1]));
}

// single-MUFU tanh (sm_75+ baseline PTX)
__device__ __forceinline__ float fast_tanh(float x) {
    float y;
    asm("tanh.approx.f32 %0, %1;" : "=f"(y) : "f"(x));
    return y;
}

// Stage = one K-128 chunk: A(128x128) two 16K halves + B(64x128) two 8K halves
#define STAGE 49152u
#define NSTAGE 4
#define SMEM_BYTES (NSTAGE * STAGE)   // 196608 <= 227KB cap, 1 CTA/SM

// ---------------------------------------------------------------------------
// xproj: g_T = emb @ Wx0 + b0   (fp32, M=10000 K=100 N=512)
// ---------------------------------------------------------------------------
__global__ void __launch_bounds__(256)
xproj_kernel(const float* __restrict__ emb, const float* __restrict__ Wx0,
             const float* __restrict__ b0)
{
    __shared__ float As[20][68];
    __shared__ float Bs[20][68];
    const int m0 = blockIdx.x * 64, n0 = blockIdx.y * 64;
    const int tid = threadIdx.x, tx = tid & 15, ty = tid >> 4;
    float acc[4][4] = {};
    for (int k0 = 0; k0 < EMBED; k0 += 20) {
        for (int i = tid; i < 64 * 20; i += 256) {
            int m = i / 20, k = i % 20;
            int gm = m0 + m;
            As[k][m] = (gm < VOCAB) ? emb[gm * EMBED + k0 + k] : 0.0f;
        }
        for (int i = tid; i < 20 * 64; i += 256) {
            int k = i / 64, n = i % 64;
            Bs[k][n] = Wx0[(k0 + k) * UNITS + n0 + n];
        }
        __syncthreads();
        #pragma unroll
        for (int kk = 0; kk < 20; ++kk) {
            float a[4], b[4];
            #pragma unroll
            for (int i = 0; i < 4; ++i) a[i] = As[kk][ty * 4 + i];
            #pragma unroll
            for (int j = 0; j < 4; ++j) b[j] = Bs[kk][tx * 4 + j];
            #pragma unroll
            for (int i = 0; i < 4; ++i)
                #pragma unroll
                for (int j = 0; j < 4; ++j)
                    acc[i][j] = fmaf(a[i], b[j], acc[i][j]);
        }
        __syncthreads();
    }
    #pragma unroll
    for (int i = 0; i < 4; ++i) {
        int row = m0 + ty * 4 + i;
        if (row >= VOCAB) continue;
        #pragma unroll
        for (int j = 0; j < 4; ++j) {
            int col = n0 + tx * 4 + j;
            g_T[row * UNITS + col] = acc[i][j] + b0[col];
        }
    }
}

// ---------------------------------------------------------------------------
// transpose + convert weights: g_W[m][n*512+k] = fp16(W[k*512+n])
// ---------------------------------------------------------------------------
__global__ void __launch_bounds__(256)
conv_weights(const float* __restrict__ a0, const float* __restrict__ a1,
             const float* __restrict__ a2, const float* __restrict__ a3,
             const float* __restrict__ a4)
{
    int i = blockIdx.x * 256 + threadIdx.x;   // i = k*512+n
    int k = i >> 9, n = i & 511;
    const float* src[5] = {a0, a1, a2, a3, a4};
    #pragma unroll
    for (int m = 0; m < 5; ++m)
        g_W[m][n * UNITS + k] = __float2half_rn(src[m][i]);
}

__global__ void init_states()
{
    int i = blockIdx.x * blockDim.x + threadIdx.x;
    const __half z = __float2half(0.0f);
    #pragma unroll
    for (int l = 0; l < 3; ++l)
        g_s[l][0][i] = z;
    if (i < 16) g_bar[i] = 0;   // reset barriers on every launch/replay
}

// ---------------------------------------------------------------------------
// stage loader: A (128 x 128) + B (64 x 128) fp16, two 64-col halves each,
// SW128 swizzled 128B rows. One commit_group per stage.
// ---------------------------------------------------------------------------
__device__ __forceinline__ void load_stage(uint32_t base,
    const __half* __restrict__ A, const __half* __restrict__ B,
    int m0, int n0, int k0, int tid)
{
    #pragma unroll
    for (int h = 0; h < 2; ++h) {
        const int kh = k0 + h * 64;
        const uint32_t ab = base + h * 16384u;
        const uint32_t bb = base + 32768u + h * 8192u;
        #pragma unroll
        for (int i = 0; i < 4; ++i) {           // A half: 1024 x 16B
            int idx = tid + i * 256;
            int row = idx >> 3, g = idx & 7;
            uint32_t d = swz((uint32_t)(row * 128 + g * 16));
            CP16(ab + d, A + (size_t)(m0 + row) * UNITS + kh + g * 8);
        }
        #pragma unroll
        for (int i = 0; i < 2; ++i) {           // B half: 512 x 16B
            int idx = tid + i * 256;
            int row = idx >> 3, g = idx & 7;
            uint32_t d = swz((uint32_t)(row * 128 + g * 16));
            CP16(bb + d, B + (size_t)(n0 + row) * UNITS + kh + g * 8);
        }
    }
    asm volatile("cp.async.commit_group;" ::: "memory");
}

// ---------------------------------------------------------------------------
// fragment loader: sub-iteration s in [0,8) = (h = s>>2, ks = s&3)
// ---------------------------------------------------------------------------
__device__ __forceinline__ void load_frag(uint32_t stb, int s,
    uint32_t (&fa)[2][4], uint32_t (&fb)[2][4],
    int a_row, int a_colb, int b_row, int b_colb)
{
    const int h = s >> 2, ks = s & 3;
    const uint32_t Ab = stb + (uint32_t)h * 16384u;
    const uint32_t Bb = stb + 32768u + (uint32_t)h * 8192u;
    #pragma unroll
    for (int mt = 0; mt < 2; ++mt) {
        uint32_t off = swz((uint32_t)((a_row + mt * 16) * 128 + a_colb + ks * 32));
        ldsm4(fa[mt], Ab + off);
    }
    #pragma unroll
    for (int bt = 0; bt < 2; ++bt) {
        uint32_t off = swz((uint32_t)((b_row + bt * 16) * 128 + b_colb + ks * 32));
        ldsm4(fb[bt], Bb + off);
    }
}

// ---------------------------------------------------------------------------
// group barrier wait: poll until all 8 CTAs of this m-group signaled `target`
// completed (t,layer) instances.
// ---------------------------------------------------------------------------
__device__ __forceinline__ void bar_wait(int grp, int target, int tid)
{
    if (tid == 0) {
        const int tgt = 8 * target;
        unsigned ns = 8;
        for (;;) {
            int v;
            asm volatile("ld.acquire.gpu.s32 %0, [%1];"
                         : "=r"(v) : "l"(&g_bar[grp]));
            if (v >= tgt) break;
            __nanosleep(ns);
            if (ns < 128) ns <<= 1;
        }
    }
    __syncthreads();
}

// ---------------------------------------------------------------------------
// persistent RNN: grid (8 n, 16 m) = 128 co-resident CTAs (1/SM).
// R12 structure; two deltas:
//  - layer 0 waits AFTER its mainloop (all its GEMM data is old; the wait is
//    needed only before the epilogue's WAR store) — skew hidden under GEMM.
//  - epilogue add-operands (token T-rows / bias) prefetched into registers
//    before the primes (launch-constant data).
// Layers 1/2 keep the R12 pre-mainloop wait.
// ---------------------------------------------------------------------------
__global__ void __launch_bounds__(256, 1)
rnn_persistent(const int* __restrict__ tokens,
               const float* __restrict__ b1, const float* __restrict__ b2)
{
    extern __shared__ __align__(1024) char smem[];
    const uint32_t sb = smem_u32(smem);
    const int tid = threadIdx.x, wid = tid >> 5, lane = tid & 31;
    const int n0 = blockIdx.x * 64, m0 = blockIdx.y * 128;
    const int grp = blockIdx.y;

    // warp layout: 4 m-warps x 2 n-warps; warp tile 32x32
    const int wm = (wid & 3) * 32;
    const int wn = (wid >> 2) * 32;
    const int sel = lane >> 3, rowin = lane & 7;
    const int a_row  = wm + (sel & 1) * 8 + rowin;
    const int a_colb = (sel >> 1) * 16;
    const int b_row  = wn + (sel >> 1) * 8 + rowin;
    const int b_colb = (sel & 1) * 16;
    const int grpq = lane >> 2, qd = (lane & 3) * 2;

    int bidx = 0;   // completed (t,layer) instances group-wide (uniform)

    for (int t = 0; t < SEQ; ++t) {
        const int p = t & 1;
        #pragma unroll 1
        for (int layer = 0; layer < 3; ++layer) {
            const __half *A0, *B0, *A1, *B1;
            int nmat;
            const float* bias;
            if (layer == 0) {
                nmat = 1; bias = nullptr;
                A0 = g_s[0][p];  B0 = g_W[0];      // s0(t-1) @ Wh0  (old data)
                A1 = A0;         B1 = B0;
            } else {
                nmat = 2;
                int wx = (layer == 1) ? 1 : 3;
                bias = (layer == 1) ? b1 : b2;
                A0 = g_s[layer][p];          B0 = g_W[wx + 1];  // Wh half (old)
                A1 = g_s[layer - 1][p ^ 1];  B1 = g_W[wx];      // Wx half (fresh)
            }
            __half* outp = g_s[layer][p ^ 1];
            const __half* Asrc[2] = {A0, A1};
            const __half* Bsrc[2] = {B0, B1};
            const int NC = nmat * 4;   // K-128 stages

            // ---- prefetch epilogue add-operands (launch-constant data) ----
            float2 adv[2][4];
            #pragma unroll
            for (int mt = 0; mt < 2; ++mt) {
                const int r0 = m0 + wm + mt * 16 + grpq;
                const float* tp;
                if (layer == 0)
                    tp = g_T + (size_t)tokens[(size_t)r0 * SEQ + t] * UNITS;
                else
                    tp = bias;
                #pragma unroll
                for (int j = 0; j < 4; ++j)
                    adv[mt][j] = *(const float2*)(tp + n0 + wn + j * 8 + qd);
            }
            float2 adv2[2][4];   // second row (r0+8) operand
            #pragma unroll
            for (int mt = 0; mt < 2; ++mt) {
                const int r1 = m0 + wm + mt * 16 + grpq + 8;
                const float* tp;
                if (layer == 0)
                    tp = g_T + (size_t)tokens[(size_t)r1 * SEQ + t] * UNITS;
                else
                    tp = bias;
                #pragma unroll
                for (int j = 0; j < 4; ++j)
                    adv2[mt][j] = *(const float2*)(tp + n0 + wn + j * 8 + qd);
            }

            // ---- prime chunks 0,1,2 (old data only; guaranteed by the wait
            //      executed at the previous instance) ----
            load_stage(sb + 0 * STAGE, A0, B0, m0, n0, 0, tid);
            load_stage(sb + 1 * STAGE, A0, B0, m0, n0, 128, tid);
            load_stage(sb + 2 * STAGE, A0, B0, m0, n0, 256, tid);

            // layers 1/2: R12 placement — wait before the mainloop (the fresh
            // Wx-half load at nc==4 needs the producers' signals).
            if (layer > 0)
                bar_wait(grp, bidx, tid);

            float acc[2][4][4] = {};

            for (int c = 0; c < NC; ++c) {
                asm volatile("cp.async.wait_group 2;" ::: "memory");
                __syncthreads();

                const int nc = c + 3;
                if (nc < NC) {
                    load_stage(sb + (nc % NSTAGE) * STAGE,
                               Asrc[nc >> 2], Bsrc[nc >> 2],
                               m0, n0, (nc & 3) * 128, tid);
                } else {
                    asm volatile("cp.async.commit_group;" ::: "memory");
                }

                const uint32_t stb = sb + (uint32_t)(c % NSTAGE) * STAGE;

                // register double-buffered fragment pipeline over 8 sub-iters
                uint32_t fa[2][2][4], fb[2][2][4];
                load_frag(stb, 0, fa[0], fb[0], a_row, a_colb, b_row, b_colb);
                #pragma unroll
                for (int s = 0; s < 8; ++s) {
                    const int cur = s & 1;
                    if (s < 7)
                        load_frag(stb, s + 1, fa[cur ^ 1], fb[cur ^ 1],
                                  a_row, a_colb, b_row, b_colb);
                    #pragma unroll
                    for (int mt = 0; mt < 2; ++mt)
                        #pragma unroll
                        for (int j = 0; j < 4; ++j)
                            mma16816(acc[mt][j], fa[cur][mt],
                                     &fb[cur][j >> 1][(j & 1) * 2]);
                }
            }

            // layer 0: entire mainloop read old data — the group wait is only
            // needed before the epilogue's WAR-hazardous store (hidden under
            // the GEMM above).
            if (layer == 0)
                bar_wait(grp, bidx, tid);

            // ---- epilogue: add prefetched T/bias, MUFU tanh, fp16 store ----
            #pragma unroll
            for (int mt = 0; mt < 2; ++mt) {
                const int r0 = m0 + wm + mt * 16 + grpq;
                const int r1 = r0 + 8;
                #pragma unroll
                for (int j = 0; j < 4; ++j) {
                    const int c = n0 + wn + j * 8 + qd;
                    __half2 p0 = __floats2half2_rn(
                        fast_tanh(acc[mt][j][0] + adv[mt][j].x),
                        fast_tanh(acc[mt][j][1] + adv[mt][j].y));
                    __half2 p1 = __floats2half2_rn(
                        fast_tanh(acc[mt][j][2] + adv2[mt][j].x),
                        fast_tanh(acc[mt][j][3] + adv2[mt][j].y));
                    *reinterpret_cast<__half2*>(outp + (size_t)r0 * UNITS + c) = p0;
                    *reinterpret_cast<__half2*>(outp + (size_t)r1 * UNITS + c) = p1;
                }
            }

            // ---- signal completion ----
            __syncthreads();
            if (tid == 0) {
                __threadfence();
                atomicAdd(&g_bar[grp], 1);
            }
            ++bidx;
        }
    }
}

// ---------------------------------------------------------------------------
// head: out[b] = sigmoid( s2[b,:] . Wout + bout )
// ---------------------------------------------------------------------------
__global__ void __launch_bounds__(256)
head_kernel(const float* __restrict__ Wout, const float* __restrict__ bout,
            float* __restrict__ out)
{
    const __half* s2 = g_s[2][0];   // SEQ even -> final state in phase 0
    int row  = blockIdx.x * 8 + (threadIdx.x >> 5);
    int lane = threadIdx.x & 31;
    float sum = 0.0f;
    #pragma unroll 4
    for (int k = lane; k < UNITS; k += 32)
        sum += __half2float(s2[(size_t)row * UNITS + k]) * Wout[k];
    #pragma unroll
    for (int o = 16; o; o >>= 1)
        sum += __shfl_xor_sync(0xFFFFFFFFu, sum, o);
    if (lane == 0) {
        float logit = sum + bout[0];
        out[row] = __fdividef(1.0f, 1.0f + __expf(-logit));
    }
}

// ---------------------------------------------------------------------------
extern "C" void kernel_launch(void* const* d_in, const int* in_sizes, int n_in,
                              void* d_out, int out_size)
{
    const int*   tokens = (const int*)  d_in[0];
    const float* emb    = (const float*)d_in[1];
    const float* Wx0    = (const float*)d_in[2];
    const float* Wh0    = (const float*)d_in[3];
    const float* b0     = (const float*)d_in[4];
    const float* Wx1    = (const float*)d_in[5];
    const float* Wh1    = (const float*)d_in[6];
    const float* b1     = (const float*)d_in[7];
    const float* Wx2    = (const float*)d_in[8];
    const float* Wh2    = (const float*)d_in[9];
    const float* b2     = (const float*)d_in[10];
    const float* Wout   = (const float*)d_in[11];
    const float* bout   = (const float*)d_in[12];
    float* out = (float*)d_out;

    cudaFuncSetAttribute(rnn_persistent, cudaFuncAttributeMaxDynamicSharedMemorySize,
                         SMEM_BYTES);

    // prologue
    xproj_kernel<<<dim3((VOCAB + 63) / 64, UNITS / 64), 256>>>(emb, Wx0, b0);
    conv_weights<<<(UNITS * UNITS) / 256, 256>>>(Wh0, Wx1, Wh1, Wx2, Wh2);
    init_states<<<(BATCH * UNITS) / 256, 256>>>();

    // the whole 80x3 recurrence in one persistent launch
    dim3 grid(UNITS / 64, BATCH / 128);   // (8 n, 16 m) = 128 CTAs, 1/SM
    rnn_persistent<<<grid, 256, SMEM_BYTES>>>(tokens, b1, b2);

    head_kernel<<<BATCH / 8, 256>>>(Wout, bout, out);
}